// round 1
// baseline (speedup 1.0000x reference)
#include <cuda_runtime.h>
#include <cuda_bf16.h>
#include <math.h>

// ---------------- problem constants ----------------
constexpr int B = 16, S = 512, D = 768, H = 12, FF = 3072, L = 4;
constexpr int DH = 64;          // head dim
constexpr int NREL = 129;       // 2*64+1 clipped relative positions
constexpr float SCALE = 0.125f; // 1/sqrt(64)
constexpr float LN_EPS = 1e-12f;

constexpr size_t BS   = (size_t)B * S;          // 8192 tokens
constexpr size_t BSD  = BS * D;                 // 6.29M
constexpr size_t BHS  = (size_t)B * H * S;      // 98304 attention rows
constexpr size_t BHSS = BHS * S;                // 50.3M scores

// ---------------- device scratch (static, allowed) ----------------
__device__ float g_x[BSD];
__device__ float g_q[BSD];
__device__ float g_k[BSD];
__device__ float g_v[BSD];
__device__ float g_scores[BHSS];        // scores -> probs (in place)
__device__ float g_qtab[BHS * NREL];    // layout [B,S,H,NREL]
__device__ float g_ptab[BHS * NREL];    // layout [B,S,H,NREL]
__device__ float g_ctx[BSD];
__device__ float g_tmp[BSD];
__device__ float g_attn[BSD];
__device__ float g_ff[BS * FF];
__device__ float g_table[NREL * DH];    // 129 distinct rel-pos rows

// ---------------- helpers ----------------
__device__ __forceinline__ float block_reduce_sum(float v, float* red) {
    int t = threadIdx.x;
    red[t] = v; __syncthreads();
    for (int o = 128; o > 0; o >>= 1) {
        if (t < o) red[t] += red[t + o];
        __syncthreads();
    }
    float r = red[0]; __syncthreads();
    return r;
}

// ---------------- table build: table[i][d] = rel[128][64+i][d] ----------------
__global__ void build_table(const float* __restrict__ rel, float* __restrict__ table) {
    int i = blockIdx.x * 256 + threadIdx.x;
    if (i < NREL * DH) {
        int r = i / DH, d = i % DH;
        table[i] = rel[((size_t)128 * S + (64 + r)) * DH + d];
    }
}

// ---------------- embedding + layernorm ----------------
__global__ __launch_bounds__(256) void embed_ln(
    const int* __restrict__ ids, const int* __restrict__ tti,
    const float* __restrict__ we, const float* __restrict__ te,
    const float* __restrict__ w, const float* __restrict__ bb,
    float* __restrict__ out)
{
    __shared__ float red[256];
    int m = blockIdx.x, t = threadIdx.x;
    int id = ids[m], t2 = tti[m];
    const float* wr = we + (size_t)id * D;
    const float* tr = te + (size_t)t2 * D;
    float vals[3]; float s = 0.f;
    #pragma unroll
    for (int i = 0; i < 3; i++) { int d = t + i * 256; vals[i] = wr[d] + tr[d]; s += vals[i]; }
    float mean = block_reduce_sum(s, red) * (1.f / D);
    float vs = 0.f;
    #pragma unroll
    for (int i = 0; i < 3; i++) { float dd = vals[i] - mean; vs += dd * dd; }
    float var = block_reduce_sum(vs, red) * (1.f / D);
    float rstd = rsqrtf(var + LN_EPS);
    #pragma unroll
    for (int i = 0; i < 3; i++) {
        int d = t + i * 256;
        out[(size_t)m * D + d] = (vals[i] - mean) * rstd * w[d] + bb[d];
    }
}

// ---------------- generic layernorm ----------------
__global__ __launch_bounds__(256) void ln_kernel(
    const float* __restrict__ x, const float* __restrict__ w,
    const float* __restrict__ bb, float* __restrict__ out)
{
    __shared__ float red[256];
    int m = blockIdx.x, t = threadIdx.x;
    const float* xr = x + (size_t)m * D;
    float vals[3]; float s = 0.f;
    #pragma unroll
    for (int i = 0; i < 3; i++) { vals[i] = xr[t + i * 256]; s += vals[i]; }
    float mean = block_reduce_sum(s, red) * (1.f / D);
    float vs = 0.f;
    #pragma unroll
    for (int i = 0; i < 3; i++) { float dd = vals[i] - mean; vs += dd * dd; }
    float var = block_reduce_sum(vs, red) * (1.f / D);
    float rstd = rsqrtf(var + LN_EPS);
    #pragma unroll
    for (int i = 0; i < 3; i++) {
        int d = t + i * 256;
        out[(size_t)m * D + d] = (vals[i] - mean) * rstd * w[d] + bb[d];
    }
}

// ---------------- GEMM NT: C[m,n] = sum_k A[m,k] * W[n,k] (+bias)(+res)(gelu) ----------------
__global__ __launch_bounds__(256) void gemm_nt(
    const float* __restrict__ A, const float* __restrict__ W,
    const float* __restrict__ bias, const float* __restrict__ res,
    float* __restrict__ C, int M, int N, int K, int act)
{
    __shared__ float As[16][65];
    __shared__ float Bs[16][65];
    const int bm = blockIdx.y * 64, bn = blockIdx.x * 64;
    const int t = threadIdx.x, tx = t & 15, ty = t >> 4;
    float acc[4][4] = {};
    for (int k0 = 0; k0 < K; k0 += 16) {
        #pragma unroll
        for (int l = 0; l < 4; l++) {
            int idx = t + l * 256;
            int r = idx >> 4, c = idx & 15;
            int m = bm + r, kk = k0 + c;
            As[c][r] = (m < M && kk < K) ? A[(size_t)m * K + kk] : 0.f;
        }
        #pragma unroll
        for (int l = 0; l < 4; l++) {
            int idx = t + l * 256;
            int r = idx >> 4, c = idx & 15;
            int n = bn + r, kk = k0 + c;
            Bs[c][r] = (n < N && kk < K) ? W[(size_t)n * K + kk] : 0.f;
        }
        __syncthreads();
        #pragma unroll
        for (int kk = 0; kk < 16; kk++) {
            float a[4], bv[4];
            #pragma unroll
            for (int i = 0; i < 4; i++) a[i] = As[kk][ty * 4 + i];
            #pragma unroll
            for (int j = 0; j < 4; j++) bv[j] = Bs[kk][tx * 4 + j];
            #pragma unroll
            for (int i = 0; i < 4; i++)
                #pragma unroll
                for (int j = 0; j < 4; j++) acc[i][j] += a[i] * bv[j];
        }
        __syncthreads();
    }
    #pragma unroll
    for (int i = 0; i < 4; i++) {
        int m = bm + ty * 4 + i;
        if (m >= M) continue;
        #pragma unroll
        for (int j = 0; j < 4; j++) {
            int n = bn + tx * 4 + j;
            if (n >= N) continue;
            float v = acc[i][j];
            if (bias) v += bias[n];
            if (res)  v += res[(size_t)m * N + n];
            if (act)  v = 0.5f * v * (1.f + erff(v * 0.70710678118654752f));
            C[(size_t)m * N + n] = v;
        }
    }
}

// ---------------- GEMM NN (small): C[m,n] = sum_k A[m,k] * Bm[k,n] ----------------
__global__ __launch_bounds__(256) void gemm_nn_small(
    const float* __restrict__ A, const float* __restrict__ Bm,
    float* __restrict__ C, int M, int N, int K)
{
    __shared__ float As[16][65];
    __shared__ float Bs[16][65];
    const int bm = blockIdx.y * 64, bn = blockIdx.x * 64;
    const int t = threadIdx.x, tx = t & 15, ty = t >> 4;
    float acc[4][4] = {};
    for (int k0 = 0; k0 < K; k0 += 16) {
        #pragma unroll
        for (int l = 0; l < 4; l++) {
            int idx = t + l * 256;
            int r = idx >> 4, c = idx & 15;
            int m = bm + r, kk = k0 + c;
            As[c][r] = (m < M && kk < K) ? A[(size_t)m * K + kk] : 0.f;
        }
        #pragma unroll
        for (int l = 0; l < 4; l++) {
            int idx = t + l * 256;
            int r = idx >> 6, c = idx & 63;
            int kk = k0 + r, n = bn + c;
            Bs[r][c] = (kk < K && n < N) ? Bm[(size_t)kk * N + n] : 0.f;
        }
        __syncthreads();
        #pragma unroll
        for (int kk = 0; kk < 16; kk++) {
            float a[4], bv[4];
            #pragma unroll
            for (int i = 0; i < 4; i++) a[i] = As[kk][ty * 4 + i];
            #pragma unroll
            for (int j = 0; j < 4; j++) bv[j] = Bs[kk][tx * 4 + j];
            #pragma unroll
            for (int i = 0; i < 4; i++)
                #pragma unroll
                for (int j = 0; j < 4; j++) acc[i][j] += a[i] * bv[j];
        }
        __syncthreads();
    }
    #pragma unroll
    for (int i = 0; i < 4; i++) {
        int m = bm + ty * 4 + i;
        if (m >= M) continue;
        #pragma unroll
        for (int j = 0; j < 4; j++) {
            int n = bn + tx * 4 + j;
            if (n >= N) continue;
            C[(size_t)m * N + n] = acc[i][j];
        }
    }
}

// ---------------- scores: (Q·K + qtab gather) * scale + mask ----------------
__global__ __launch_bounds__(256) void scores_kernel(
    const float* __restrict__ Q, const float* __restrict__ Kt,
    const float* __restrict__ qtab, const int* __restrict__ mask,
    float* __restrict__ scores)
{
    __shared__ float As[16][65];
    __shared__ float Bs[16][65];
    const int bh = blockIdx.z, b = bh / H, h = bh % H;
    const float* Qb = Q + (size_t)b * S * D + h * DH;
    const float* Kb = Kt + (size_t)b * S * D + h * DH;
    const int q0 = blockIdx.y * 64, k0 = blockIdx.x * 64;
    const int t = threadIdx.x, tx = t & 15, ty = t >> 4;
    float acc[4][4] = {};
    for (int c0 = 0; c0 < DH; c0 += 16) {
        #pragma unroll
        for (int l = 0; l < 4; l++) {
            int idx = t + l * 256;
            int r = idx >> 4, c = idx & 15;
            As[c][r] = Qb[(size_t)(q0 + r) * D + c0 + c];
        }
        #pragma unroll
        for (int l = 0; l < 4; l++) {
            int idx = t + l * 256;
            int r = idx >> 4, c = idx & 15;
            Bs[c][r] = Kb[(size_t)(k0 + r) * D + c0 + c];
        }
        __syncthreads();
        #pragma unroll
        for (int kk = 0; kk < 16; kk++) {
            float a[4], bv[4];
            #pragma unroll
            for (int i = 0; i < 4; i++) a[i] = As[kk][ty * 4 + i];
            #pragma unroll
            for (int j = 0; j < 4; j++) bv[j] = Bs[kk][tx * 4 + j];
            #pragma unroll
            for (int i = 0; i < 4; i++)
                #pragma unroll
                for (int j = 0; j < 4; j++) acc[i][j] += a[i] * bv[j];
        }
        __syncthreads();
    }
    #pragma unroll
    for (int i = 0; i < 4; i++) {
        int q = q0 + ty * 4 + i;
        #pragma unroll
        for (int j = 0; j < 4; j++) {
            int k = k0 + tx * 4 + j;
            int relk = k - q;
            relk = relk < -64 ? -64 : (relk > 64 ? 64 : relk);
            float qt = qtab[(((size_t)b * S + q) * H + h) * NREL + relk + 64];
            float mb = (1.f - (float)mask[b * S + k]) * -10000.f;
            scores[((size_t)bh * S + q) * S + k] = (acc[i][j] + qt) * SCALE + mb;
        }
    }
}

// ---------------- softmax (in place) + ptab binning ----------------
__global__ __launch_bounds__(256) void softmax_kernel(
    float* __restrict__ scores, float* __restrict__ ptab)
{
    __shared__ float red[256];
    const int row = blockIdx.x;            // (b*H+h)*S + q
    const int q = row % S, bh = row / S;
    const int b = bh / H, h = bh % H;
    float* sr = scores + (size_t)row * S;
    const int t = threadIdx.x;
    float v0 = sr[t], v1 = sr[t + 256];

    // max
    float m = fmaxf(v0, v1);
    red[t] = m; __syncthreads();
    for (int o = 128; o > 0; o >>= 1) { if (t < o) red[t] = fmaxf(red[t], red[t + o]); __syncthreads(); }
    m = red[0]; __syncthreads();

    float e0 = expf(v0 - m), e1 = expf(v1 - m);
    float s = block_reduce_sum(e0 + e1, red);
    float inv = 1.f / s;
    float p0 = e0 * inv, p1 = e1 * inv;
    sr[t] = p0; sr[t + 256] = p1;

    // clip-bin sums: left k <= q-64, right k >= q+64
    float left = 0.f, right = 0.f;
    if (t <= q - 64)       left += p0;
    if (t + 256 <= q - 64) left += p1;
    if (t >= q + 64)       right += p0;
    if (t + 256 >= q + 64) right += p1;
    left  = block_reduce_sum(left,  red);
    right = block_reduce_sum(right, red);

    size_t pbase = (((size_t)b * S + q) * H + h) * NREL;
    if (t == 0) { ptab[pbase] = left; ptab[pbase + 128] = right; }
    // middle bins j=1..127: exactly one k = q + j - 64
    if (t >= 1 && t <= 127) {
        int k = q + t - 64;
        ptab[pbase + t] = (k >= 0 && k < S) ? sr[k] : 0.f;
    }
}

// ---------------- ctx += probs @ V (batched over b,h), into (B,S,D) layout ----------------
__global__ __launch_bounds__(256) void ctx_pv_kernel(
    const float* __restrict__ P, const float* __restrict__ V,
    float* __restrict__ ctx)
{
    __shared__ float As[16][65];
    __shared__ float Bs[16][65];
    const int bh = blockIdx.z, b = bh / H, h = bh % H;
    const float* Pb = P + (size_t)bh * S * S;
    const float* Vb = V + (size_t)b * S * D + h * DH;
    const int q0 = blockIdx.x * 64;
    const int t = threadIdx.x, tx = t & 15, ty = t >> 4;
    float acc[4][4] = {};
    for (int k0 = 0; k0 < S; k0 += 16) {
        #pragma unroll
        for (int l = 0; l < 4; l++) {
            int idx = t + l * 256;
            int r = idx >> 4, c = idx & 15;
            As[c][r] = Pb[(size_t)(q0 + r) * S + k0 + c];
        }
        #pragma unroll
        for (int l = 0; l < 4; l++) {
            int idx = t + l * 256;
            int r = idx >> 6, c = idx & 63;
            Bs[r][c] = Vb[(size_t)(k0 + r) * D + c];
        }
        __syncthreads();
        #pragma unroll
        for (int kk = 0; kk < 16; kk++) {
            float a[4], bv[4];
            #pragma unroll
            for (int i = 0; i < 4; i++) a[i] = As[kk][ty * 4 + i];
            #pragma unroll
            for (int j = 0; j < 4; j++) bv[j] = Bs[kk][tx * 4 + j];
            #pragma unroll
            for (int i = 0; i < 4; i++)
                #pragma unroll
                for (int j = 0; j < 4; j++) acc[i][j] += a[i] * bv[j];
        }
        __syncthreads();
    }
    #pragma unroll
    for (int i = 0; i < 4; i++) {
        int q = q0 + ty * 4 + i;
        #pragma unroll
        for (int j = 0; j < 4; j++) {
            int d = tx * 4 + j;
            size_t o = ((size_t)b * S + q) * D + h * DH + d;
            ctx[o] += acc[i][j];
        }
    }
}

// ---------------- launch ----------------
extern "C" void kernel_launch(void* const* d_in, const int* in_sizes, int n_in,
                              void* d_out, int out_size)
{
    const int*   ids     = (const int*)d_in[0];
    const int*   amask   = (const int*)d_in[1];
    const int*   tti     = (const int*)d_in[2];
    const float* wemb    = (const float*)d_in[3];
    const float* temb    = (const float*)d_in[4];
    const float* elnw    = (const float*)d_in[5];
    const float* elnb    = (const float*)d_in[6];
    const float* qw      = (const float*)d_in[7];
    const float* qb      = (const float*)d_in[8];
    const float* kw      = (const float*)d_in[9];
    const float* kb      = (const float*)d_in[10];
    const float* vw      = (const float*)d_in[11];
    const float* vb      = (const float*)d_in[12];
    const float* rel     = (const float*)d_in[13];
    const float* ow      = (const float*)d_in[14];
    const float* ob      = (const float*)d_in[15];
    const float* alnw    = (const float*)d_in[16];
    const float* alnb    = (const float*)d_in[17];
    const float* iw      = (const float*)d_in[18];
    const float* ib      = (const float*)d_in[19];
    const float* dw      = (const float*)d_in[20];
    const float* db      = (const float*)d_in[21];
    const float* olnw    = (const float*)d_in[22];
    const float* olnb    = (const float*)d_in[23];
    float* out = (float*)d_out;

    float *x, *q, *k, *v, *sc, *qt, *pt, *ctx, *tmp, *attn, *ff, *tab;
    cudaGetSymbolAddress((void**)&x,    g_x);
    cudaGetSymbolAddress((void**)&q,    g_q);
    cudaGetSymbolAddress((void**)&k,    g_k);
    cudaGetSymbolAddress((void**)&v,    g_v);
    cudaGetSymbolAddress((void**)&sc,   g_scores);
    cudaGetSymbolAddress((void**)&qt,   g_qtab);
    cudaGetSymbolAddress((void**)&pt,   g_ptab);
    cudaGetSymbolAddress((void**)&ctx,  g_ctx);
    cudaGetSymbolAddress((void**)&tmp,  g_tmp);
    cudaGetSymbolAddress((void**)&attn, g_attn);
    cudaGetSymbolAddress((void**)&ff,   g_ff);
    cudaGetSymbolAddress((void**)&tab,  g_table);

    build_table<<<(NREL * DH + 255) / 256, 256>>>(rel, tab);
    embed_ln<<<(int)BS, 256>>>(ids, tti, wemb, temb, elnw, elnb, x);

    const dim3 gP(D / 64, (int)(BS / 64));          // projection grids (12,128)
    const dim3 gF1(FF / 64, (int)(BS / 64));        // FFN1 (48,128)
    const dim3 gQT((NREL + 63) / 64, (int)(BS * H / 64));  // (3,1536)
    const dim3 gCR(1, (int)(BS * H / 64));          // ctx_rel (1,1536)
    const dim3 gSC(S / 64, S / 64, B * H);          // (8,8,192)
    const dim3 gPV(S / 64, 1, B * H);               // (8,1,192)

    for (int l = 0; l < L; l++) {
        const float* qwl = qw + (size_t)l * D * D;
        const float* kwl = kw + (size_t)l * D * D;
        const float* vwl = vw + (size_t)l * D * D;
        const float* owl = ow + (size_t)l * D * D;
        const float* iwl = iw + (size_t)l * FF * D;
        const float* dwl = dw + (size_t)l * D * FF;

        gemm_nt<<<gP, 256>>>(x, qwl, qb + l * D, nullptr, q, (int)BS, D, D, 0);
        gemm_nt<<<gP, 256>>>(x, kwl, kb + l * D, nullptr, k, (int)BS, D, D, 0);
        gemm_nt<<<gP, 256>>>(x, vwl, vb + l * D, nullptr, v, (int)BS, D, D, 0);

        // qtab = Q(reshaped B*S*H x 64) @ table^T   (129 outputs per row)
        gemm_nt<<<gQT, 256>>>(q, tab, nullptr, nullptr, qt, (int)(BS * H), NREL, DH, 0);

        scores_kernel<<<gSC, 256>>>(q, k, qt, amask, sc);
        softmax_kernel<<<(int)BHS, 256>>>(sc, pt);

        // ctx = ptab @ table  (rel-position values), then += probs @ V
        gemm_nn_small<<<gCR, 256>>>(pt, tab, ctx, (int)(BS * H), DH, NREL);
        ctx_pv_kernel<<<gPV, 256>>>(sc, v, ctx);

        // attention output projection + residual, then LN
        gemm_nt<<<gP, 256>>>(ctx, owl, ob + l * D, x, tmp, (int)BS, D, D, 0);
        ln_kernel<<<(int)BS, 256>>>(tmp, alnw + l * D, alnb + l * D, attn);

        // FFN
        gemm_nt<<<gF1, 256>>>(attn, iwl, ib + l * FF, nullptr, ff, (int)BS, FF, D, 1);
        gemm_nt<<<gP, 256>>>(ff, dwl, db + l * D, attn, tmp, (int)BS, D, FF, 0);
        ln_kernel<<<(int)BS, 256>>>(tmp, olnw + l * D, olnb + l * D,
                                    (l == L - 1) ? out : x);
    }
}

// round 2
// speedup vs baseline: 1.7025x; 1.7025x over previous
#include <cuda_runtime.h>
#include <cuda_bf16.h>
#include <math.h>

// ---------------- problem constants ----------------
constexpr int B = 16, S = 512, D = 768, H = 12, FF = 3072, L = 4;
constexpr int DH = 64;
constexpr int NREL = 129;
constexpr float SCALE = 0.125f;
constexpr float LN_EPS = 1e-12f;

constexpr size_t BS   = (size_t)B * S;
constexpr size_t BSD  = BS * D;
constexpr size_t BHS  = (size_t)B * H * S;
constexpr size_t BHSS = BHS * S;

// ---------------- device scratch ----------------
__device__ float g_x[BSD];
__device__ float g_q[BSD];
__device__ float g_k[BSD];
__device__ float g_v[BSD];
__device__ float g_scores[BHSS];
__device__ float g_qtab[BHS * NREL];
__device__ float g_ptab[BHS * NREL];
__device__ float g_ctx[BSD];
__device__ float g_tmp[BSD];
__device__ float g_attn[BSD];
__device__ float g_ff[BS * FF];
__device__ float g_table[NREL * DH];

// ---------------- helpers ----------------
__device__ __forceinline__ float block_reduce_sum(float v, float* red) {
    int t = threadIdx.x;
    red[t] = v; __syncthreads();
    for (int o = 128; o > 0; o >>= 1) {
        if (t < o) red[t] += red[t + o];
        __syncthreads();
    }
    float r = red[0]; __syncthreads();
    return r;
}

__global__ void build_table(const float* __restrict__ rel, float* __restrict__ table) {
    int i = blockIdx.x * 256 + threadIdx.x;
    if (i < NREL * DH) {
        int r = i / DH, d = i % DH;
        table[i] = rel[((size_t)128 * S + (64 + r)) * DH + d];
    }
}

// ---------------- embedding + layernorm ----------------
__global__ __launch_bounds__(256) void embed_ln(
    const int* __restrict__ ids, const int* __restrict__ tti,
    const float* __restrict__ we, const float* __restrict__ te,
    const float* __restrict__ w, const float* __restrict__ bb,
    float* __restrict__ out)
{
    __shared__ float red[256];
    int m = blockIdx.x, t = threadIdx.x;
    int id = ids[m], t2 = tti[m];
    const float* wr = we + (size_t)id * D;
    const float* tr = te + (size_t)t2 * D;
    float vals[3]; float s = 0.f;
    #pragma unroll
    for (int i = 0; i < 3; i++) { int d = t + i * 256; vals[i] = wr[d] + tr[d]; s += vals[i]; }
    float mean = block_reduce_sum(s, red) * (1.f / D);
    float vs = 0.f;
    #pragma unroll
    for (int i = 0; i < 3; i++) { float dd = vals[i] - mean; vs += dd * dd; }
    float var = block_reduce_sum(vs, red) * (1.f / D);
    float rstd = rsqrtf(var + LN_EPS);
    #pragma unroll
    for (int i = 0; i < 3; i++) {
        int d = t + i * 256;
        out[(size_t)m * D + d] = (vals[i] - mean) * rstd * w[d] + bb[d];
    }
}

__global__ __launch_bounds__(256) void ln_kernel(
    const float* __restrict__ x, const float* __restrict__ w,
    const float* __restrict__ bb, float* __restrict__ out)
{
    __shared__ float red[256];
    int m = blockIdx.x, t = threadIdx.x;
    const float* xr = x + (size_t)m * D;
    float vals[3]; float s = 0.f;
    #pragma unroll
    for (int i = 0; i < 3; i++) { vals[i] = xr[t + i * 256]; s += vals[i]; }
    float mean = block_reduce_sum(s, red) * (1.f / D);
    float vs = 0.f;
    #pragma unroll
    for (int i = 0; i < 3; i++) { float dd = vals[i] - mean; vs += dd * dd; }
    float var = block_reduce_sum(vs, red) * (1.f / D);
    float rstd = rsqrtf(var + LN_EPS);
    #pragma unroll
    for (int i = 0; i < 3; i++) {
        int d = t + i * 256;
        out[(size_t)m * D + d] = (vals[i] - mean) * rstd * w[d] + bb[d];
    }
}

// ======================================================================
// Big GEMM NT: C[m,n] = sum_k A[m,k]*W[n,k] (+bias)(+res)(gelu)
// 128x128 block tile, 8x8 microtile, K-tile 16. Requires M%128==0, N%128==0,
// K%16==0, 16B-aligned rows (K%4==0).
// ======================================================================
__global__ __launch_bounds__(256) void gemm128_nt(
    const float* __restrict__ A, const float* __restrict__ W,
    const float* __restrict__ bias, const float* __restrict__ res,
    float* __restrict__ C, int M, int N, int K, int act)
{
    __shared__ float As[16][132];
    __shared__ float Bs[16][132];
    const int bm = blockIdx.y * 128, bn = blockIdx.x * 128;
    const int t = threadIdx.x, tx = t & 15, ty = t >> 4;
    float acc[8][8] = {};

    for (int k0 = 0; k0 < K; k0 += 16) {
        #pragma unroll
        for (int l = 0; l < 2; l++) {
            int idx = t + l * 256;
            int row = idx >> 2, c4 = (idx & 3) * 4;
            float4 va = *(const float4*)&A[(size_t)(bm + row) * K + k0 + c4];
            As[c4 + 0][row] = va.x; As[c4 + 1][row] = va.y;
            As[c4 + 2][row] = va.z; As[c4 + 3][row] = va.w;
            float4 vb = *(const float4*)&W[(size_t)(bn + row) * K + k0 + c4];
            Bs[c4 + 0][row] = vb.x; Bs[c4 + 1][row] = vb.y;
            Bs[c4 + 2][row] = vb.z; Bs[c4 + 3][row] = vb.w;
        }
        __syncthreads();
        #pragma unroll
        for (int kk = 0; kk < 16; kk++) {
            float a[8], bv[8];
            *(float4*)&a[0]  = *(const float4*)&As[kk][ty * 8];
            *(float4*)&a[4]  = *(const float4*)&As[kk][ty * 8 + 4];
            *(float4*)&bv[0] = *(const float4*)&Bs[kk][tx * 8];
            *(float4*)&bv[4] = *(const float4*)&Bs[kk][tx * 8 + 4];
            #pragma unroll
            for (int i = 0; i < 8; i++)
                #pragma unroll
                for (int j = 0; j < 8; j++) acc[i][j] += a[i] * bv[j];
        }
        __syncthreads();
    }

    #pragma unroll
    for (int i = 0; i < 8; i++) {
        int m = bm + ty * 8 + i;
        #pragma unroll
        for (int j = 0; j < 8; j += 4) {
            int n = bn + tx * 8 + j;
            float4 v = make_float4(acc[i][j], acc[i][j+1], acc[i][j+2], acc[i][j+3]);
            if (bias) {
                float4 bv = *(const float4*)&bias[n];
                v.x += bv.x; v.y += bv.y; v.z += bv.z; v.w += bv.w;
            }
            if (res) {
                float4 rv = *(const float4*)&res[(size_t)m * N + n];
                v.x += rv.x; v.y += rv.y; v.z += rv.z; v.w += rv.w;
            }
            if (act) {
                v.x = 0.5f * v.x * (1.f + erff(v.x * 0.70710678118654752f));
                v.y = 0.5f * v.y * (1.f + erff(v.y * 0.70710678118654752f));
                v.z = 0.5f * v.z * (1.f + erff(v.z * 0.70710678118654752f));
                v.w = 0.5f * v.w * (1.f + erff(v.w * 0.70710678118654752f));
            }
            *(float4*)&C[(size_t)m * N + n] = v;
        }
    }
}

// ======================================================================
// Scores: 128x128 tile over (q,k), K=DH=64, epilogue adds qtab gather,
// scale and mask bias.
// ======================================================================
__global__ __launch_bounds__(256) void scores128(
    const float* __restrict__ Q, const float* __restrict__ Kt,
    const float* __restrict__ qtab, const int* __restrict__ mask,
    float* __restrict__ scores)
{
    __shared__ float As[16][132];
    __shared__ float Bs[16][132];
    const int bh = blockIdx.z, b = bh / H, h = bh % H;
    const float* Qb = Q + (size_t)b * S * D + h * DH;
    const float* Kb = Kt + (size_t)b * S * D + h * DH;
    const int q0 = blockIdx.y * 128, k0b = blockIdx.x * 128;
    const int t = threadIdx.x, tx = t & 15, ty = t >> 4;
    float acc[8][8] = {};

    for (int k0 = 0; k0 < DH; k0 += 16) {
        #pragma unroll
        for (int l = 0; l < 2; l++) {
            int idx = t + l * 256;
            int row = idx >> 2, c4 = (idx & 3) * 4;
            float4 va = *(const float4*)&Qb[(size_t)(q0 + row) * D + k0 + c4];
            As[c4 + 0][row] = va.x; As[c4 + 1][row] = va.y;
            As[c4 + 2][row] = va.z; As[c4 + 3][row] = va.w;
            float4 vb = *(const float4*)&Kb[(size_t)(k0b + row) * D + k0 + c4];
            Bs[c4 + 0][row] = vb.x; Bs[c4 + 1][row] = vb.y;
            Bs[c4 + 2][row] = vb.z; Bs[c4 + 3][row] = vb.w;
        }
        __syncthreads();
        #pragma unroll
        for (int kk = 0; kk < 16; kk++) {
            float a[8], bv[8];
            *(float4*)&a[0]  = *(const float4*)&As[kk][ty * 8];
            *(float4*)&a[4]  = *(const float4*)&As[kk][ty * 8 + 4];
            *(float4*)&bv[0] = *(const float4*)&Bs[kk][tx * 8];
            *(float4*)&bv[4] = *(const float4*)&Bs[kk][tx * 8 + 4];
            #pragma unroll
            for (int i = 0; i < 8; i++)
                #pragma unroll
                for (int j = 0; j < 8; j++) acc[i][j] += a[i] * bv[j];
        }
        __syncthreads();
    }

    #pragma unroll
    for (int i = 0; i < 8; i++) {
        int q = q0 + ty * 8 + i;
        const float* qtr = qtab + (((size_t)b * S + q) * H + h) * NREL;
        #pragma unroll
        for (int j = 0; j < 8; j++) {
            int k = k0b + tx * 8 + j;
            int relk = k - q;
            relk = relk < -64 ? -64 : (relk > 64 ? 64 : relk);
            float qt = qtr[relk + 64];
            float mb = (1.f - (float)mask[b * S + k]) * -10000.f;
            scores[((size_t)bh * S + q) * S + k] = (acc[i][j] + qt) * SCALE + mb;
        }
    }
}

// ======================================================================
// ctx += probs @ V : 128(m) x 64(n) tile, 8x4 microtile, K=512
// ======================================================================
__global__ __launch_bounds__(256) void ctx_pv128(
    const float* __restrict__ P, const float* __restrict__ V,
    float* __restrict__ ctx)
{
    __shared__ float As[16][132];
    __shared__ float Bs[16][68];
    const int bh = blockIdx.z, b = bh / H, h = bh % H;
    const float* Pb = P + (size_t)bh * S * S;
    const float* Vb = V + (size_t)b * S * D + h * DH;
    const int q0 = blockIdx.x * 128;
    const int t = threadIdx.x, tx = t & 15, ty = t >> 4;
    float acc[8][4] = {};

    for (int k0 = 0; k0 < S; k0 += 16) {
        #pragma unroll
        for (int l = 0; l < 2; l++) {
            int idx = t + l * 256;
            int row = idx >> 2, c4 = (idx & 3) * 4;
            float4 va = *(const float4*)&Pb[(size_t)(q0 + row) * S + k0 + c4];
            As[c4 + 0][row] = va.x; As[c4 + 1][row] = va.y;
            As[c4 + 2][row] = va.z; As[c4 + 3][row] = va.w;
        }
        {
            int r = t >> 4, c = (t & 15) * 4;
            float4 vb = *(const float4*)&Vb[(size_t)(k0 + r) * D + c];
            *(float4*)&Bs[r][c] = vb;
        }
        __syncthreads();
        #pragma unroll
        for (int kk = 0; kk < 16; kk++) {
            float a[8], bv[4];
            *(float4*)&a[0]  = *(const float4*)&As[kk][ty * 8];
            *(float4*)&a[4]  = *(const float4*)&As[kk][ty * 8 + 4];
            *(float4*)&bv[0] = *(const float4*)&Bs[kk][tx * 4];
            #pragma unroll
            for (int i = 0; i < 8; i++)
                #pragma unroll
                for (int j = 0; j < 4; j++) acc[i][j] += a[i] * bv[j];
        }
        __syncthreads();
    }

    #pragma unroll
    for (int i = 0; i < 8; i++) {
        int q = q0 + ty * 8 + i;
        int n = tx * 4;
        size_t o = ((size_t)b * S + q) * D + h * DH + n;
        float4 cur = *(float4*)&ctx[o];
        cur.x += acc[i][0]; cur.y += acc[i][1];
        cur.z += acc[i][2]; cur.w += acc[i][3];
        *(float4*)&ctx[o] = cur;
    }
}

// ---------------- small guarded GEMMs (odd shapes) ----------------
__global__ __launch_bounds__(256) void gemm_nt(
    const float* __restrict__ A, const float* __restrict__ W,
    const float* __restrict__ bias, const float* __restrict__ res,
    float* __restrict__ C, int M, int N, int K, int act)
{
    __shared__ float As[16][65];
    __shared__ float Bs[16][65];
    const int bm = blockIdx.y * 64, bn = blockIdx.x * 64;
    const int t = threadIdx.x, tx = t & 15, ty = t >> 4;
    float acc[4][4] = {};
    for (int k0 = 0; k0 < K; k0 += 16) {
        #pragma unroll
        for (int l = 0; l < 4; l++) {
            int idx = t + l * 256;
            int r = idx >> 4, c = idx & 15;
            int m = bm + r, kk = k0 + c;
            As[c][r] = (m < M && kk < K) ? A[(size_t)m * K + kk] : 0.f;
        }
        #pragma unroll
        for (int l = 0; l < 4; l++) {
            int idx = t + l * 256;
            int r = idx >> 4, c = idx & 15;
            int n = bn + r, kk = k0 + c;
            Bs[c][r] = (n < N && kk < K) ? W[(size_t)n * K + kk] : 0.f;
        }
        __syncthreads();
        #pragma unroll
        for (int kk = 0; kk < 16; kk++) {
            float a[4], bv[4];
            #pragma unroll
            for (int i = 0; i < 4; i++) a[i] = As[kk][ty * 4 + i];
            #pragma unroll
            for (int j = 0; j < 4; j++) bv[j] = Bs[kk][tx * 4 + j];
            #pragma unroll
            for (int i = 0; i < 4; i++)
                #pragma unroll
                for (int j = 0; j < 4; j++) acc[i][j] += a[i] * bv[j];
        }
        __syncthreads();
    }
    #pragma unroll
    for (int i = 0; i < 4; i++) {
        int m = bm + ty * 4 + i;
        if (m >= M) continue;
        #pragma unroll
        for (int j = 0; j < 4; j++) {
            int n = bn + tx * 4 + j;
            if (n >= N) continue;
            float v = acc[i][j];
            if (bias) v += bias[n];
            if (res)  v += res[(size_t)m * N + n];
            if (act)  v = 0.5f * v * (1.f + erff(v * 0.70710678118654752f));
            C[(size_t)m * N + n] = v;
        }
    }
}

__global__ __launch_bounds__(256) void gemm_nn_small(
    const float* __restrict__ A, const float* __restrict__ Bm,
    float* __restrict__ C, int M, int N, int K)
{
    __shared__ float As[16][65];
    __shared__ float Bs[16][65];
    const int bm = blockIdx.y * 64, bn = blockIdx.x * 64;
    const int t = threadIdx.x, tx = t & 15, ty = t >> 4;
    float acc[4][4] = {};
    for (int k0 = 0; k0 < K; k0 += 16) {
        #pragma unroll
        for (int l = 0; l < 4; l++) {
            int idx = t + l * 256;
            int r = idx >> 4, c = idx & 15;
            int m = bm + r, kk = k0 + c;
            As[c][r] = (m < M && kk < K) ? A[(size_t)m * K + kk] : 0.f;
        }
        #pragma unroll
        for (int l = 0; l < 4; l++) {
            int idx = t + l * 256;
            int r = idx >> 6, c = idx & 63;
            int kk = k0 + r, n = bn + c;
            Bs[r][c] = (kk < K && n < N) ? Bm[(size_t)kk * N + n] : 0.f;
        }
        __syncthreads();
        #pragma unroll
        for (int kk = 0; kk < 16; kk++) {
            float a[4], bv[4];
            #pragma unroll
            for (int i = 0; i < 4; i++) a[i] = As[kk][ty * 4 + i];
            #pragma unroll
            for (int j = 0; j < 4; j++) bv[j] = Bs[kk][tx * 4 + j];
            #pragma unroll
            for (int i = 0; i < 4; i++)
                #pragma unroll
                for (int j = 0; j < 4; j++) acc[i][j] += a[i] * bv[j];
        }
        __syncthreads();
    }
    #pragma unroll
    for (int i = 0; i < 4; i++) {
        int m = bm + ty * 4 + i;
        if (m >= M) continue;
        #pragma unroll
        for (int j = 0; j < 4; j++) {
            int n = bn + tx * 4 + j;
            if (n >= N) continue;
            C[(size_t)m * N + n] = acc[i][j];
        }
    }
}

// ---------------- softmax (in place) + ptab binning ----------------
__global__ __launch_bounds__(256) void softmax_kernel(
    float* __restrict__ scores, float* __restrict__ ptab)
{
    __shared__ float red[256];
    const int row = blockIdx.x;
    const int q = row % S, bh = row / S;
    const int b = bh / H, h = bh % H;
    float* sr = scores + (size_t)row * S;
    const int t = threadIdx.x;
    float v0 = sr[t], v1 = sr[t + 256];

    float m = fmaxf(v0, v1);
    red[t] = m; __syncthreads();
    for (int o = 128; o > 0; o >>= 1) { if (t < o) red[t] = fmaxf(red[t], red[t + o]); __syncthreads(); }
    m = red[0]; __syncthreads();

    float e0 = expf(v0 - m), e1 = expf(v1 - m);
    float s = block_reduce_sum(e0 + e1, red);
    float inv = 1.f / s;
    float p0 = e0 * inv, p1 = e1 * inv;
    sr[t] = p0; sr[t + 256] = p1;

    float left = 0.f, right = 0.f;
    if (t <= q - 64)       left += p0;
    if (t + 256 <= q - 64) left += p1;
    if (t >= q + 64)       right += p0;
    if (t + 256 >= q + 64) right += p1;
    left  = block_reduce_sum(left,  red);
    right = block_reduce_sum(right, red);

    size_t pbase = (((size_t)b * S + q) * H + h) * NREL;
    if (t == 0) { ptab[pbase] = left; ptab[pbase + 128] = right; }
    if (t >= 1 && t <= 127) {
        int k = q + t - 64;
        ptab[pbase + t] = (k >= 0 && k < S) ? sr[k] : 0.f;
    }
}

// ---------------- launch ----------------
extern "C" void kernel_launch(void* const* d_in, const int* in_sizes, int n_in,
                              void* d_out, int out_size)
{
    const int*   ids     = (const int*)d_in[0];
    const int*   amask   = (const int*)d_in[1];
    const int*   tti     = (const int*)d_in[2];
    const float* wemb    = (const float*)d_in[3];
    const float* temb    = (const float*)d_in[4];
    const float* elnw    = (const float*)d_in[5];
    const float* elnb    = (const float*)d_in[6];
    const float* qw      = (const float*)d_in[7];
    const float* qb      = (const float*)d_in[8];
    const float* kw      = (const float*)d_in[9];
    const float* kb      = (const float*)d_in[10];
    const float* vw      = (const float*)d_in[11];
    const float* vb      = (const float*)d_in[12];
    const float* rel     = (const float*)d_in[13];
    const float* ow      = (const float*)d_in[14];
    const float* ob      = (const float*)d_in[15];
    const float* alnw    = (const float*)d_in[16];
    const float* alnb    = (const float*)d_in[17];
    const float* iw      = (const float*)d_in[18];
    const float* ib      = (const float*)d_in[19];
    const float* dw      = (const float*)d_in[20];
    const float* db      = (const float*)d_in[21];
    const float* olnw    = (const float*)d_in[22];
    const float* olnb    = (const float*)d_in[23];
    float* out = (float*)d_out;

    float *x, *q, *k, *v, *sc, *qt, *pt, *ctx, *tmp, *attn, *ff, *tab;
    cudaGetSymbolAddress((void**)&x,    g_x);
    cudaGetSymbolAddress((void**)&q,    g_q);
    cudaGetSymbolAddress((void**)&k,    g_k);
    cudaGetSymbolAddress((void**)&v,    g_v);
    cudaGetSymbolAddress((void**)&sc,   g_scores);
    cudaGetSymbolAddress((void**)&qt,   g_qtab);
    cudaGetSymbolAddress((void**)&pt,   g_ptab);
    cudaGetSymbolAddress((void**)&ctx,  g_ctx);
    cudaGetSymbolAddress((void**)&tmp,  g_tmp);
    cudaGetSymbolAddress((void**)&attn, g_attn);
    cudaGetSymbolAddress((void**)&ff,   g_ff);
    cudaGetSymbolAddress((void**)&tab,  g_table);

    build_table<<<(NREL * DH + 255) / 256, 256>>>(rel, tab);
    embed_ln<<<(int)BS, 256>>>(ids, tti, wemb, temb, elnw, elnb, x);

    const dim3 gP(D / 128, (int)(BS / 128));               // (6,64)
    const dim3 gF1(FF / 128, (int)(BS / 128));             // (24,64)
    const dim3 gQT((NREL + 63) / 64, (int)(BS * H / 64));  // (3,1536)
    const dim3 gCR(1, (int)(BS * H / 64));                 // (1,1536)
    const dim3 gSC(S / 128, S / 128, B * H);               // (4,4,192)
    const dim3 gPV(S / 128, 1, B * H);                     // (4,1,192)

    for (int l = 0; l < L; l++) {
        const float* qwl = qw + (size_t)l * D * D;
        const float* kwl = kw + (size_t)l * D * D;
        const float* vwl = vw + (size_t)l * D * D;
        const float* owl = ow + (size_t)l * D * D;
        const float* iwl = iw + (size_t)l * FF * D;
        const float* dwl = dw + (size_t)l * D * FF;

        gemm128_nt<<<gP, 256>>>(x, qwl, qb + l * D, nullptr, q, (int)BS, D, D, 0);
        gemm128_nt<<<gP, 256>>>(x, kwl, kb + l * D, nullptr, k, (int)BS, D, D, 0);
        gemm128_nt<<<gP, 256>>>(x, vwl, vb + l * D, nullptr, v, (int)BS, D, D, 0);

        // qtab = Q(reshaped B*S*H x 64) @ table^T
        gemm_nt<<<gQT, 256>>>(q, tab, nullptr, nullptr, qt, (int)(BS * H), NREL, DH, 0);

        scores128<<<gSC, 256>>>(q, k, qt, amask, sc);
        softmax_kernel<<<(int)BHS, 256>>>(sc, pt);

        // ctx = ptab @ table, then += probs @ V
        gemm_nn_small<<<gCR, 256>>>(pt, tab, ctx, (int)(BS * H), DH, NREL);
        ctx_pv128<<<gPV, 256>>>(sc, v, ctx);

        gemm128_nt<<<gP, 256>>>(ctx, owl, ob + l * D, x, tmp, (int)BS, D, D, 0);
        ln_kernel<<<(int)BS, 256>>>(tmp, alnw + l * D, alnb + l * D, attn);

        gemm128_nt<<<gF1, 256>>>(attn, iwl, ib + l * FF, nullptr, ff, (int)BS, FF, D, 1);
        gemm128_nt<<<gP, 256>>>(ff, dwl, db + l * D, attn, tmp, (int)BS, D, FF, 0);
        ln_kernel<<<(int)BS, 256>>>(tmp, olnw + l * D, olnb + l * D,
                                    (l == L - 1) ? out : x);
    }
}

// round 3
// speedup vs baseline: 2.4589x; 1.4442x over previous
#include <cuda_runtime.h>
#include <cuda_bf16.h>
#include <math.h>
#include <stdint.h>

// ---------------- problem constants ----------------
constexpr int B = 16, S = 512, D = 768, H = 12, FF = 3072, L = 4;
constexpr int DH = 64;
constexpr int NREL = 129;
constexpr float SCALE = 0.125f;
constexpr float LN_EPS = 1e-12f;

constexpr size_t BS   = (size_t)B * S;
constexpr size_t BSD  = BS * D;
constexpr size_t BHS  = (size_t)B * H * S;
constexpr size_t BHSS = BHS * S;

// ---------------- device scratch ----------------
__device__ float g_x[BSD];
__device__ float g_q[BSD];
__device__ float g_k[BSD];
__device__ float g_v[BSD];
__device__ float g_scores[BHSS];
__device__ float g_qtab[BHS * NREL];
__device__ float g_ptab[BHS * NREL];
__device__ float g_ctx[BSD];
__device__ float g_tmp[BSD];
__device__ float g_attn[BSD];
__device__ float g_ff[BS * FF];
__device__ float g_table[NREL * DH];

// bf16 split buffers
constexpr size_t WSZ = (size_t)L * D * D;    // 2.36M per tensor
constexpr size_t WFF = (size_t)L * FF * D;   // 9.44M
__device__ __align__(256) __nv_bfloat16 g_wqh[WSZ], g_wql[WSZ];
__device__ __align__(256) __nv_bfloat16 g_wkh[WSZ], g_wkl[WSZ];
__device__ __align__(256) __nv_bfloat16 g_wvh[WSZ], g_wvl[WSZ];
__device__ __align__(256) __nv_bfloat16 g_woh[WSZ], g_wol[WSZ];
__device__ __align__(256) __nv_bfloat16 g_wih[WFF], g_wil[WFF];
__device__ __align__(256) __nv_bfloat16 g_wdh[WFF], g_wdl[WFF];
__device__ __align__(256) __nv_bfloat16 g_ah[BS * FF], g_al[BS * FF];

// ---------------- helpers ----------------
__device__ __forceinline__ float block_reduce_sum(float v, float* red) {
    int t = threadIdx.x;
    red[t] = v; __syncthreads();
    for (int o = 128; o > 0; o >>= 1) {
        if (t < o) red[t] += red[t + o];
        __syncthreads();
    }
    float r = red[0]; __syncthreads();
    return r;
}

__global__ void build_table(const float* __restrict__ rel, float* __restrict__ table) {
    int i = blockIdx.x * 256 + threadIdx.x;
    if (i < NREL * DH) {
        int r = i / DH, d = i % DH;
        table[i] = rel[((size_t)128 * S + (64 + r)) * DH + d];
    }
}

// split fp32 -> bf16 hi + bf16 lo (residual). n4 = count/4.
__global__ __launch_bounds__(256) void split_bf16(
    const float* __restrict__ in, __nv_bfloat16* __restrict__ hi,
    __nv_bfloat16* __restrict__ lo, int n4)
{
    int i = blockIdx.x * 256 + threadIdx.x;
    if (i >= n4) return;
    float4 v = ((const float4*)in)[i];
    __nv_bfloat16 h0 = __float2bfloat16_rn(v.x);
    __nv_bfloat16 h1 = __float2bfloat16_rn(v.y);
    __nv_bfloat16 h2 = __float2bfloat16_rn(v.z);
    __nv_bfloat16 h3 = __float2bfloat16_rn(v.w);
    __nv_bfloat16 l0 = __float2bfloat16_rn(v.x - __bfloat162float(h0));
    __nv_bfloat16 l1 = __float2bfloat16_rn(v.y - __bfloat162float(h1));
    __nv_bfloat16 l2 = __float2bfloat16_rn(v.z - __bfloat162float(h2));
    __nv_bfloat16 l3 = __float2bfloat16_rn(v.w - __bfloat162float(h3));
    __nv_bfloat162* hp = (__nv_bfloat162*)hi;
    __nv_bfloat162* lp = (__nv_bfloat162*)lo;
    hp[i * 2 + 0] = __nv_bfloat162(h0, h1);
    hp[i * 2 + 1] = __nv_bfloat162(h2, h3);
    lp[i * 2 + 0] = __nv_bfloat162(l0, l1);
    lp[i * 2 + 1] = __nv_bfloat162(l2, l3);
}

// ---------------- mma primitives ----------------
__device__ __forceinline__ void mma16816(float* d, const uint32_t* a, const uint32_t* b) {
    asm volatile(
        "mma.sync.aligned.m16n8k16.row.col.f32.bf16.bf16.f32 "
        "{%0,%1,%2,%3}, {%4,%5,%6,%7}, {%8,%9}, {%0,%1,%2,%3};\n"
        : "+f"(d[0]), "+f"(d[1]), "+f"(d[2]), "+f"(d[3])
        : "r"(a[0]), "r"(a[1]), "r"(a[2]), "r"(a[3]), "r"(b[0]), "r"(b[1]));
}
__device__ __forceinline__ void ldsm4(uint32_t* r, uint32_t addr) {
    asm volatile("ldmatrix.sync.aligned.m8n8.x4.shared.b16 {%0,%1,%2,%3}, [%4];\n"
        : "=r"(r[0]), "=r"(r[1]), "=r"(r[2]), "=r"(r[3]) : "r"(addr));
}

// ======================================================================
// Split-bf16 tensor-core GEMM NT: C = (Ah+Al)(Wh+Wl)^T (dropping Al*Wl)
// 128x128 block, 8 warps (2m x 4n), warp tile 64x32, k-tile 16.
// Requires M%128==0, N%128==0, K%16==0.
// ======================================================================
constexpr int ASTR = 24;   // padded bf16 row stride (conflict-free ldmatrix)

__global__ __launch_bounds__(256) void gemm_mma_nt(
    const __nv_bfloat16* __restrict__ Ah, const __nv_bfloat16* __restrict__ Al,
    const __nv_bfloat16* __restrict__ Wh, const __nv_bfloat16* __restrict__ Wl,
    const float* __restrict__ bias, const float* __restrict__ res,
    float* __restrict__ C, int M, int N, int K, int act)
{
    __shared__ __nv_bfloat16 sAh[128 * ASTR], sAl[128 * ASTR];
    __shared__ __nv_bfloat16 sBh[128 * ASTR], sBl[128 * ASTR];
    const int bm = blockIdx.y * 128, bn = blockIdx.x * 128;
    const int t = threadIdx.x, lane = t & 31, w = t >> 5;
    const int wm = (w & 1) * 64, wn = (w >> 1) * 32;

    // global staging: thread t loads 8 bf16 (16B) per matrix per k-tile
    const int grow = t >> 1, gcol = (t & 1) * 8;
    const __nv_bfloat16* pAh = Ah + (size_t)(bm + grow) * K + gcol;
    const __nv_bfloat16* pAl = Al + (size_t)(bm + grow) * K + gcol;
    const __nv_bfloat16* pWh = Wh + (size_t)(bn + grow) * K + gcol;
    const __nv_bfloat16* pWl = Wl + (size_t)(bn + grow) * K + gcol;

    const uint32_t bAh = (uint32_t)__cvta_generic_to_shared(sAh);
    const uint32_t bAl = (uint32_t)__cvta_generic_to_shared(sAl);
    const uint32_t bBh = (uint32_t)__cvta_generic_to_shared(sBh);
    const uint32_t bBl = (uint32_t)__cvta_generic_to_shared(sBl);
    const int soff = grow * ASTR + gcol;

    float acc[4][4][4];
    #pragma unroll
    for (int i = 0; i < 4; i++)
        #pragma unroll
        for (int j = 0; j < 4; j++)
            #pragma unroll
            for (int r = 0; r < 4; r++) acc[i][j][r] = 0.f;

    // ldmatrix addresses (bytes)
    uint32_t aoff[4], boff[2];
    #pragma unroll
    for (int mi = 0; mi < 4; mi++)
        aoff[mi] = (uint32_t)(((wm + mi * 16 + (lane & 15)) * ASTR + ((lane >> 4) << 3)) * 2);
    #pragma unroll
    for (int ni2 = 0; ni2 < 2; ni2++)
        boff[ni2] = (uint32_t)(((wn + ni2 * 16 + (lane & 7) + ((lane >> 4) << 3)) * ASTR
                               + (((lane >> 3) & 1) << 3)) * 2);

    const int nk = K / 16;
    uint4 rAh = *(const uint4*)pAh; pAh += 16;
    uint4 rAl = *(const uint4*)pAl; pAl += 16;
    uint4 rWh = *(const uint4*)pWh; pWh += 16;
    uint4 rWl = *(const uint4*)pWl; pWl += 16;

    for (int kt = 0; kt < nk; kt++) {
        *(uint4*)&sAh[soff] = rAh;
        *(uint4*)&sAl[soff] = rAl;
        *(uint4*)&sBh[soff] = rWh;
        *(uint4*)&sBl[soff] = rWl;
        __syncthreads();
        if (kt + 1 < nk) {
            rAh = *(const uint4*)pAh; pAh += 16;
            rAl = *(const uint4*)pAl; pAl += 16;
            rWh = *(const uint4*)pWh; pWh += 16;
            rWl = *(const uint4*)pWl; pWl += 16;
        }

        uint32_t ah[4][4], al[4][4], bh[4][2], bl[4][2];
        #pragma unroll
        for (int mi = 0; mi < 4; mi++) {
            ldsm4(ah[mi], bAh + aoff[mi]);
            ldsm4(al[mi], bAl + aoff[mi]);
        }
        #pragma unroll
        for (int ni2 = 0; ni2 < 2; ni2++) {
            uint32_t tmp4[4];
            ldsm4(tmp4, bBh + boff[ni2]);
            bh[ni2 * 2][0] = tmp4[0]; bh[ni2 * 2][1] = tmp4[1];
            bh[ni2 * 2 + 1][0] = tmp4[2]; bh[ni2 * 2 + 1][1] = tmp4[3];
            ldsm4(tmp4, bBl + boff[ni2]);
            bl[ni2 * 2][0] = tmp4[0]; bl[ni2 * 2][1] = tmp4[1];
            bl[ni2 * 2 + 1][0] = tmp4[2]; bl[ni2 * 2 + 1][1] = tmp4[3];
        }
        #pragma unroll
        for (int mi = 0; mi < 4; mi++)
            #pragma unroll
            for (int ni = 0; ni < 4; ni++) {
                mma16816(acc[mi][ni], ah[mi], bh[ni]);
                mma16816(acc[mi][ni], ah[mi], bl[ni]);
                mma16816(acc[mi][ni], al[mi], bh[ni]);
            }
        __syncthreads();
    }

    // epilogue: c0,c1 -> (row, n..n+1); c2,c3 -> (row+8, n..n+1)
    #pragma unroll
    for (int mi = 0; mi < 4; mi++) {
        int m0 = bm + wm + mi * 16 + (lane >> 2);
        #pragma unroll
        for (int ni = 0; ni < 4; ni++) {
            int n = bn + wn + ni * 8 + (lane & 3) * 2;
            float2 v0 = make_float2(acc[mi][ni][0], acc[mi][ni][1]);
            float2 v1 = make_float2(acc[mi][ni][2], acc[mi][ni][3]);
            if (bias) {
                float2 bv = *(const float2*)&bias[n];
                v0.x += bv.x; v0.y += bv.y; v1.x += bv.x; v1.y += bv.y;
            }
            if (res) {
                float2 r0 = *(const float2*)&res[(size_t)m0 * N + n];
                float2 r1 = *(const float2*)&res[(size_t)(m0 + 8) * N + n];
                v0.x += r0.x; v0.y += r0.y; v1.x += r1.x; v1.y += r1.y;
            }
            if (act) {
                v0.x = 0.5f * v0.x * (1.f + erff(v0.x * 0.70710678118654752f));
                v0.y = 0.5f * v0.y * (1.f + erff(v0.y * 0.70710678118654752f));
                v1.x = 0.5f * v1.x * (1.f + erff(v1.x * 0.70710678118654752f));
                v1.y = 0.5f * v1.y * (1.f + erff(v1.y * 0.70710678118654752f));
            }
            *(float2*)&C[(size_t)m0 * N + n] = v0;
            *(float2*)&C[(size_t)(m0 + 8) * N + n] = v1;
        }
    }
}

// ---------------- embedding + layernorm ----------------
__global__ __launch_bounds__(256) void embed_ln(
    const int* __restrict__ ids, const int* __restrict__ tti,
    const float* __restrict__ we, const float* __restrict__ te,
    const float* __restrict__ w, const float* __restrict__ bb,
    float* __restrict__ out)
{
    __shared__ float red[256];
    int m = blockIdx.x, t = threadIdx.x;
    int id = ids[m], t2 = tti[m];
    const float* wr = we + (size_t)id * D;
    const float* tr = te + (size_t)t2 * D;
    float vals[3]; float s = 0.f;
    #pragma unroll
    for (int i = 0; i < 3; i++) { int d = t + i * 256; vals[i] = wr[d] + tr[d]; s += vals[i]; }
    float mean = block_reduce_sum(s, red) * (1.f / D);
    float vs = 0.f;
    #pragma unroll
    for (int i = 0; i < 3; i++) { float dd = vals[i] - mean; vs += dd * dd; }
    float var = block_reduce_sum(vs, red) * (1.f / D);
    float rstd = rsqrtf(var + LN_EPS);
    #pragma unroll
    for (int i = 0; i < 3; i++) {
        int d = t + i * 256;
        out[(size_t)m * D + d] = (vals[i] - mean) * rstd * w[d] + bb[d];
    }
}

__global__ __launch_bounds__(256) void ln_kernel(
    const float* __restrict__ x, const float* __restrict__ w,
    const float* __restrict__ bb, float* __restrict__ out)
{
    __shared__ float red[256];
    int m = blockIdx.x, t = threadIdx.x;
    const float* xr = x + (size_t)m * D;
    float vals[3]; float s = 0.f;
    #pragma unroll
    for (int i = 0; i < 3; i++) { vals[i] = xr[t + i * 256]; s += vals[i]; }
    float mean = block_reduce_sum(s, red) * (1.f / D);
    float vs = 0.f;
    #pragma unroll
    for (int i = 0; i < 3; i++) { float dd = vals[i] - mean; vs += dd * dd; }
    float var = block_reduce_sum(vs, red) * (1.f / D);
    float rstd = rsqrtf(var + LN_EPS);
    #pragma unroll
    for (int i = 0; i < 3; i++) {
        int d = t + i * 256;
        out[(size_t)m * D + d] = (vals[i] - mean) * rstd * w[d] + bb[d];
    }
}

// ======================================================================
// Scores: 128x128 tile over (q,k), K=DH=64 (fp32 SIMT)
// ======================================================================
__global__ __launch_bounds__(256) void scores128(
    const float* __restrict__ Q, const float* __restrict__ Kt,
    const float* __restrict__ qtab, const int* __restrict__ mask,
    float* __restrict__ scores)
{
    __shared__ float As[16][132];
    __shared__ float Bs[16][132];
    const int bh = blockIdx.z, b = bh / H, h = bh % H;
    const float* Qb = Q + (size_t)b * S * D + h * DH;
    const float* Kb = Kt + (size_t)b * S * D + h * DH;
    const int q0 = blockIdx.y * 128, k0b = blockIdx.x * 128;
    const int t = threadIdx.x, tx = t & 15, ty = t >> 4;
    float acc[8][8] = {};

    for (int k0 = 0; k0 < DH; k0 += 16) {
        #pragma unroll
        for (int l = 0; l < 2; l++) {
            int idx = t + l * 256;
            int row = idx >> 2, c4 = (idx & 3) * 4;
            float4 va = *(const float4*)&Qb[(size_t)(q0 + row) * D + k0 + c4];
            As[c4 + 0][row] = va.x; As[c4 + 1][row] = va.y;
            As[c4 + 2][row] = va.z; As[c4 + 3][row] = va.w;
            float4 vb = *(const float4*)&Kb[(size_t)(k0b + row) * D + k0 + c4];
            Bs[c4 + 0][row] = vb.x; Bs[c4 + 1][row] = vb.y;
            Bs[c4 + 2][row] = vb.z; Bs[c4 + 3][row] = vb.w;
        }
        __syncthreads();
        #pragma unroll
        for (int kk = 0; kk < 16; kk++) {
            float a[8], bv[8];
            *(float4*)&a[0]  = *(const float4*)&As[kk][ty * 8];
            *(float4*)&a[4]  = *(const float4*)&As[kk][ty * 8 + 4];
            *(float4*)&bv[0] = *(const float4*)&Bs[kk][tx * 8];
            *(float4*)&bv[4] = *(const float4*)&Bs[kk][tx * 8 + 4];
            #pragma unroll
            for (int i = 0; i < 8; i++)
                #pragma unroll
                for (int j = 0; j < 8; j++) acc[i][j] += a[i] * bv[j];
        }
        __syncthreads();
    }

    #pragma unroll
    for (int i = 0; i < 8; i++) {
        int q = q0 + ty * 8 + i;
        const float* qtr = qtab + (((size_t)b * S + q) * H + h) * NREL;
        #pragma unroll
        for (int j = 0; j < 8; j++) {
            int k = k0b + tx * 8 + j;
            int relk = k - q;
            relk = relk < -64 ? -64 : (relk > 64 ? 64 : relk);
            float qt = qtr[relk + 64];
            float mb = (1.f - (float)mask[b * S + k]) * -10000.f;
            scores[((size_t)bh * S + q) * S + k] = (acc[i][j] + qt) * SCALE + mb;
        }
    }
}

// ======================================================================
// ctx += probs @ V
// ======================================================================
__global__ __launch_bounds__(256) void ctx_pv128(
    const float* __restrict__ P, const float* __restrict__ V,
    float* __restrict__ ctx)
{
    __shared__ float As[16][132];
    __shared__ float Bs[16][68];
    const int bh = blockIdx.z, b = bh / H, h = bh % H;
    const float* Pb = P + (size_t)bh * S * S;
    const float* Vb = V + (size_t)b * S * D + h * DH;
    const int q0 = blockIdx.x * 128;
    const int t = threadIdx.x, tx = t & 15, ty = t >> 4;
    float acc[8][4] = {};

    for (int k0 = 0; k0 < S; k0 += 16) {
        #pragma unroll
        for (int l = 0; l < 2; l++) {
            int idx = t + l * 256;
            int row = idx >> 2, c4 = (idx & 3) * 4;
            float4 va = *(const float4*)&Pb[(size_t)(q0 + row) * S + k0 + c4];
            As[c4 + 0][row] = va.x; As[c4 + 1][row] = va.y;
            As[c4 + 2][row] = va.z; As[c4 + 3][row] = va.w;
        }
        {
            int r = t >> 4, c = (t & 15) * 4;
            float4 vb = *(const float4*)&Vb[(size_t)(k0 + r) * D + c];
            *(float4*)&Bs[r][c] = vb;
        }
        __syncthreads();
        #pragma unroll
        for (int kk = 0; kk < 16; kk++) {
            float a[8], bv[4];
            *(float4*)&a[0]  = *(const float4*)&As[kk][ty * 8];
            *(float4*)&a[4]  = *(const float4*)&As[kk][ty * 8 + 4];
            *(float4*)&bv[0] = *(const float4*)&Bs[kk][tx * 4];
            #pragma unroll
            for (int i = 0; i < 8; i++)
                #pragma unroll
                for (int j = 0; j < 4; j++) acc[i][j] += a[i] * bv[j];
        }
        __syncthreads();
    }

    #pragma unroll
    for (int i = 0; i < 8; i++) {
        int q = q0 + ty * 8 + i;
        int n = tx * 4;
        size_t o = ((size_t)b * S + q) * D + h * DH + n;
        float4 cur = *(float4*)&ctx[o];
        cur.x += acc[i][0]; cur.y += acc[i][1];
        cur.z += acc[i][2]; cur.w += acc[i][3];
        *(float4*)&ctx[o] = cur;
    }
}

// ---------------- small guarded GEMMs ----------------
__global__ __launch_bounds__(256) void gemm_nt(
    const float* __restrict__ A, const float* __restrict__ W,
    const float* __restrict__ bias, const float* __restrict__ res,
    float* __restrict__ C, int M, int N, int K, int act)
{
    __shared__ float As[16][65];
    __shared__ float Bs[16][65];
    const int bm = blockIdx.y * 64, bn = blockIdx.x * 64;
    const int t = threadIdx.x, tx = t & 15, ty = t >> 4;
    float acc[4][4] = {};
    for (int k0 = 0; k0 < K; k0 += 16) {
        #pragma unroll
        for (int l = 0; l < 4; l++) {
            int idx = t + l * 256;
            int r = idx >> 4, c = idx & 15;
            int m = bm + r, kk = k0 + c;
            As[c][r] = (m < M && kk < K) ? A[(size_t)m * K + kk] : 0.f;
        }
        #pragma unroll
        for (int l = 0; l < 4; l++) {
            int idx = t + l * 256;
            int r = idx >> 4, c = idx & 15;
            int n = bn + r, kk = k0 + c;
            Bs[c][r] = (n < N && kk < K) ? W[(size_t)n * K + kk] : 0.f;
        }
        __syncthreads();
        #pragma unroll
        for (int kk = 0; kk < 16; kk++) {
            float a[4], bv[4];
            #pragma unroll
            for (int i = 0; i < 4; i++) a[i] = As[kk][ty * 4 + i];
            #pragma unroll
            for (int j = 0; j < 4; j++) bv[j] = Bs[kk][tx * 4 + j];
            #pragma unroll
            for (int i = 0; i < 4; i++)
                #pragma unroll
                for (int j = 0; j < 4; j++) acc[i][j] += a[i] * bv[j];
        }
        __syncthreads();
    }
    #pragma unroll
    for (int i = 0; i < 4; i++) {
        int m = bm + ty * 4 + i;
        if (m >= M) continue;
        #pragma unroll
        for (int j = 0; j < 4; j++) {
            int n = bn + tx * 4 + j;
            if (n >= N) continue;
            float v = acc[i][j];
            if (bias) v += bias[n];
            if (res)  v += res[(size_t)m * N + n];
            if (act)  v = 0.5f * v * (1.f + erff(v * 0.70710678118654752f));
            C[(size_t)m * N + n] = v;
        }
    }
}

__global__ __launch_bounds__(256) void gemm_nn_small(
    const float* __restrict__ A, const float* __restrict__ Bm,
    float* __restrict__ C, int M, int N, int K)
{
    __shared__ float As[16][65];
    __shared__ float Bs[16][65];
    const int bm = blockIdx.y * 64, bn = blockIdx.x * 64;
    const int t = threadIdx.x, tx = t & 15, ty = t >> 4;
    float acc[4][4] = {};
    for (int k0 = 0; k0 < K; k0 += 16) {
        #pragma unroll
        for (int l = 0; l < 4; l++) {
            int idx = t + l * 256;
            int r = idx >> 4, c = idx & 15;
            int m = bm + r, kk = k0 + c;
            As[c][r] = (m < M && kk < K) ? A[(size_t)m * K + kk] : 0.f;
        }
        #pragma unroll
        for (int l = 0; l < 4; l++) {
            int idx = t + l * 256;
            int r = idx >> 6, c = idx & 63;
            int kk = k0 + r, n = bn + c;
            Bs[r][c] = (kk < K && n < N) ? Bm[(size_t)kk * N + n] : 0.f;
        }
        __syncthreads();
        #pragma unroll
        for (int kk = 0; kk < 16; kk++) {
            float a[4], bv[4];
            #pragma unroll
            for (int i = 0; i < 4; i++) a[i] = As[kk][ty * 4 + i];
            #pragma unroll
            for (int j = 0; j < 4; j++) bv[j] = Bs[kk][tx * 4 + j];
            #pragma unroll
            for (int i = 0; i < 4; i++)
                #pragma unroll
                for (int j = 0; j < 4; j++) acc[i][j] += a[i] * bv[j];
        }
        __syncthreads();
    }
    #pragma unroll
    for (int i = 0; i < 4; i++) {
        int m = bm + ty * 4 + i;
        if (m >= M) continue;
        #pragma unroll
        for (int j = 0; j < 4; j++) {
            int n = bn + tx * 4 + j;
            if (n >= N) continue;
            C[(size_t)m * N + n] = acc[i][j];
        }
    }
}

// ---------------- softmax (in place) + ptab binning ----------------
__global__ __launch_bounds__(256) void softmax_kernel(
    float* __restrict__ scores, float* __restrict__ ptab)
{
    __shared__ float red[256];
    const int row = blockIdx.x;
    const int q = row % S, bh = row / S;
    const int b = bh / H, h = bh % H;
    float* sr = scores + (size_t)row * S;
    const int t = threadIdx.x;
    float v0 = sr[t], v1 = sr[t + 256];

    float m = fmaxf(v0, v1);
    red[t] = m; __syncthreads();
    for (int o = 128; o > 0; o >>= 1) { if (t < o) red[t] = fmaxf(red[t], red[t + o]); __syncthreads(); }
    m = red[0]; __syncthreads();

    float e0 = expf(v0 - m), e1 = expf(v1 - m);
    float s = block_reduce_sum(e0 + e1, red);
    float inv = 1.f / s;
    float p0 = e0 * inv, p1 = e1 * inv;
    sr[t] = p0; sr[t + 256] = p1;

    float left = 0.f, right = 0.f;
    if (t <= q - 64)       left += p0;
    if (t + 256 <= q - 64) left += p1;
    if (t >= q + 64)       right += p0;
    if (t + 256 >= q + 64) right += p1;
    left  = block_reduce_sum(left,  red);
    right = block_reduce_sum(right, red);

    size_t pbase = (((size_t)b * S + q) * H + h) * NREL;
    if (t == 0) { ptab[pbase] = left; ptab[pbase + 128] = right; }
    if (t >= 1 && t <= 127) {
        int k = q + t - 64;
        ptab[pbase + t] = (k >= 0 && k < S) ? sr[k] : 0.f;
    }
}

// ---------------- launch ----------------
extern "C" void kernel_launch(void* const* d_in, const int* in_sizes, int n_in,
                              void* d_out, int out_size)
{
    const int*   ids     = (const int*)d_in[0];
    const int*   amask   = (const int*)d_in[1];
    const int*   tti     = (const int*)d_in[2];
    const float* wemb    = (const float*)d_in[3];
    const float* temb    = (const float*)d_in[4];
    const float* elnw    = (const float*)d_in[5];
    const float* elnb    = (const float*)d_in[6];
    const float* qw      = (const float*)d_in[7];
    const float* qb      = (const float*)d_in[8];
    const float* kw      = (const float*)d_in[9];
    const float* kb      = (const float*)d_in[10];
    const float* vw      = (const float*)d_in[11];
    const float* vb      = (const float*)d_in[12];
    const float* rel     = (const float*)d_in[13];
    const float* ow      = (const float*)d_in[14];
    const float* ob      = (const float*)d_in[15];
    const float* alnw    = (const float*)d_in[16];
    const float* alnb    = (const float*)d_in[17];
    const float* iw      = (const float*)d_in[18];
    const float* ib      = (const float*)d_in[19];
    const float* dw      = (const float*)d_in[20];
    const float* db      = (const float*)d_in[21];
    const float* olnw    = (const float*)d_in[22];
    const float* olnb    = (const float*)d_in[23];
    float* out = (float*)d_out;

    float *x, *q, *k, *v, *sc, *qt, *pt, *ctx, *tmp, *attn, *ff, *tab;
    cudaGetSymbolAddress((void**)&x,    g_x);
    cudaGetSymbolAddress((void**)&q,    g_q);
    cudaGetSymbolAddress((void**)&k,    g_k);
    cudaGetSymbolAddress((void**)&v,    g_v);
    cudaGetSymbolAddress((void**)&sc,   g_scores);
    cudaGetSymbolAddress((void**)&qt,   g_qtab);
    cudaGetSymbolAddress((void**)&pt,   g_ptab);
    cudaGetSymbolAddress((void**)&ctx,  g_ctx);
    cudaGetSymbolAddress((void**)&tmp,  g_tmp);
    cudaGetSymbolAddress((void**)&attn, g_attn);
    cudaGetSymbolAddress((void**)&ff,   g_ff);
    cudaGetSymbolAddress((void**)&tab,  g_table);

    __nv_bfloat16 *wqh, *wql, *wkh, *wkl, *wvh, *wvl, *woh, *wol;
    __nv_bfloat16 *wih, *wil, *wdh, *wdl, *ah, *al;
    cudaGetSymbolAddress((void**)&wqh, g_wqh); cudaGetSymbolAddress((void**)&wql, g_wql);
    cudaGetSymbolAddress((void**)&wkh, g_wkh); cudaGetSymbolAddress((void**)&wkl, g_wkl);
    cudaGetSymbolAddress((void**)&wvh, g_wvh); cudaGetSymbolAddress((void**)&wvl, g_wvl);
    cudaGetSymbolAddress((void**)&woh, g_woh); cudaGetSymbolAddress((void**)&wol, g_wol);
    cudaGetSymbolAddress((void**)&wih, g_wih); cudaGetSymbolAddress((void**)&wil, g_wil);
    cudaGetSymbolAddress((void**)&wdh, g_wdh); cudaGetSymbolAddress((void**)&wdl, g_wdl);
    cudaGetSymbolAddress((void**)&ah,  g_ah);  cudaGetSymbolAddress((void**)&al,  g_al);

    build_table<<<(NREL * DH + 255) / 256, 256>>>(rel, tab);
    embed_ln<<<(int)BS, 256>>>(ids, tti, wemb, temb, elnw, elnb, x);

    // weight splits (once)
    {
        int n4 = (int)(WSZ / 4), g = (n4 + 255) / 256;
        split_bf16<<<g, 256>>>(qw, wqh, wql, n4);
        split_bf16<<<g, 256>>>(kw, wkh, wkl, n4);
        split_bf16<<<g, 256>>>(vw, wvh, wvl, n4);
        split_bf16<<<g, 256>>>(ow, woh, wol, n4);
        int n4f = (int)(WFF / 4), gf = (n4f + 255) / 256;
        split_bf16<<<gf, 256>>>(iw, wih, wil, n4f);
        split_bf16<<<gf, 256>>>(dw, wdh, wdl, n4f);
    }

    const int nD4 = (int)(BSD / 4), gD = (nD4 + 255) / 256;
    const int nF4 = (int)(BS * FF / 4), gF = (nF4 + 255) / 256;

    const dim3 gP(D / 128, (int)(BS / 128));               // (6,64)
    const dim3 gF1(FF / 128, (int)(BS / 128));             // (24,64)
    const dim3 gQT((NREL + 63) / 64, (int)(BS * H / 64));  // (3,1536)
    const dim3 gCR(1, (int)(BS * H / 64));                 // (1,1536)
    const dim3 gSC(S / 128, S / 128, B * H);               // (4,4,192)
    const dim3 gPV(S / 128, 1, B * H);                     // (4,1,192)

    for (int l = 0; l < L; l++) {
        const size_t wo = (size_t)l * D * D;
        const size_t fo = (size_t)l * FF * D;

        split_bf16<<<gD, 256>>>(x, ah, al, nD4);
        gemm_mma_nt<<<gP, 256>>>(ah, al, wqh + wo, wql + wo, qb + l * D, nullptr, q, (int)BS, D, D, 0);
        gemm_mma_nt<<<gP, 256>>>(ah, al, wkh + wo, wkl + wo, kb + l * D, nullptr, k, (int)BS, D, D, 0);
        gemm_mma_nt<<<gP, 256>>>(ah, al, wvh + wo, wvl + wo, vb + l * D, nullptr, v, (int)BS, D, D, 0);

        gemm_nt<<<gQT, 256>>>(q, tab, nullptr, nullptr, qt, (int)(BS * H), NREL, DH, 0);

        scores128<<<gSC, 256>>>(q, k, qt, amask, sc);
        softmax_kernel<<<(int)BHS, 256>>>(sc, pt);

        gemm_nn_small<<<gCR, 256>>>(pt, tab, ctx, (int)(BS * H), DH, NREL);
        ctx_pv128<<<gPV, 256>>>(sc, v, ctx);

        split_bf16<<<gD, 256>>>(ctx, ah, al, nD4);
        gemm_mma_nt<<<gP, 256>>>(ah, al, woh + wo, wol + wo, ob + l * D, x, tmp, (int)BS, D, D, 0);
        ln_kernel<<<(int)BS, 256>>>(tmp, alnw + l * D, alnb + l * D, attn);

        split_bf16<<<gD, 256>>>(attn, ah, al, nD4);
        gemm_mma_nt<<<gF1, 256>>>(ah, al, wih + fo, wil + fo, ib + l * FF, nullptr, ff, (int)BS, FF, D, 1);

        split_bf16<<<gF, 256>>>(ff, ah, al, nF4);
        gemm_mma_nt<<<gP, 256>>>(ah, al, wdh + fo, wdl + fo, db + l * D, attn, tmp, (int)BS, D, FF, 0);
        ln_kernel<<<(int)BS, 256>>>(tmp, olnw + l * D, olnb + l * D,
                                    (l == L - 1) ? out : x);
    }
}

// round 4
// speedup vs baseline: 3.1954x; 1.2995x over previous
#include <cuda_runtime.h>
#include <cuda_bf16.h>
#include <math.h>
#include <stdint.h>

// ---------------- problem constants ----------------
constexpr int B = 16, S = 512, D = 768, H = 12, FF = 3072, L = 4;
constexpr int DH = 64;
constexpr int NREL = 129;
constexpr float SCALE = 0.125f;
constexpr float LN_EPS = 1e-12f;

constexpr size_t BS   = (size_t)B * S;
constexpr size_t BSD  = BS * D;
constexpr size_t BHS  = (size_t)B * H * S;
constexpr size_t BHSS = BHS * S;

// ---------------- device scratch ----------------
__device__ float g_x[BSD];
__device__ float g_q[BSD];
__device__ float g_scores[BHSS];
__device__ float g_qtab[BHS * NREL];
__device__ float g_ptab[BHS * NREL];
__device__ float g_ctx[BSD];
__device__ float g_tmp[BSD];
__device__ float g_attn[BSD];
__device__ float g_table[NREL * DH];

// bf16 buffers
constexpr size_t WSZ = (size_t)L * D * D;
constexpr size_t WFF = (size_t)L * FF * D;
__device__ __align__(256) __nv_bfloat16 g_wqh[WSZ], g_wql[WSZ];
__device__ __align__(256) __nv_bfloat16 g_wkh[WSZ], g_wkl[WSZ];
__device__ __align__(256) __nv_bfloat16 g_wvh[WSZ], g_wvl[WSZ];
__device__ __align__(256) __nv_bfloat16 g_woh[WSZ], g_wol[WSZ];
__device__ __align__(256) __nv_bfloat16 g_wih[WFF], g_wil[WFF];
__device__ __align__(256) __nv_bfloat16 g_wdh[WFF], g_wdl[WFF];
__device__ __align__(256) __nv_bfloat16 g_xh[BSD], g_xl[BSD];
__device__ __align__(256) __nv_bfloat16 g_qh[BSD], g_ql[BSD];
__device__ __align__(256) __nv_bfloat16 g_kh[BSD], g_kl[BSD];
__device__ __align__(256) __nv_bfloat16 g_vh[BSD], g_vl[BSD];
__device__ __align__(256) __nv_bfloat16 g_ah[BSD], g_al[BSD];
__device__ __align__(256) __nv_bfloat16 g_ffh[BS * FF], g_ffl[BS * FF];
__device__ __align__(256) __nv_bfloat16 g_ph[BHSS], g_pl[BHSS];

// ---------------- helpers ----------------
__device__ __forceinline__ float block_reduce_sum(float v, float* red) {
    int t = threadIdx.x;
    red[t] = v; __syncthreads();
    for (int o = 128; o > 0; o >>= 1) {
        if (t < o) red[t] += red[t + o];
        __syncthreads();
    }
    float r = red[0]; __syncthreads();
    return r;
}

__global__ void build_table(const float* __restrict__ rel, float* __restrict__ table) {
    int i = blockIdx.x * 256 + threadIdx.x;
    if (i < NREL * DH) {
        int r = i / DH, d = i % DH;
        table[i] = rel[((size_t)128 * S + (64 + r)) * DH + d];
    }
}

__global__ __launch_bounds__(256) void split_bf16(
    const float* __restrict__ in, __nv_bfloat16* __restrict__ hi,
    __nv_bfloat16* __restrict__ lo, int n4)
{
    int i = blockIdx.x * 256 + threadIdx.x;
    if (i >= n4) return;
    float4 v = ((const float4*)in)[i];
    __nv_bfloat16 h0 = __float2bfloat16_rn(v.x);
    __nv_bfloat16 h1 = __float2bfloat16_rn(v.y);
    __nv_bfloat16 h2 = __float2bfloat16_rn(v.z);
    __nv_bfloat16 h3 = __float2bfloat16_rn(v.w);
    __nv_bfloat16 l0 = __float2bfloat16_rn(v.x - __bfloat162float(h0));
    __nv_bfloat16 l1 = __float2bfloat16_rn(v.y - __bfloat162float(h1));
    __nv_bfloat16 l2 = __float2bfloat16_rn(v.z - __bfloat162float(h2));
    __nv_bfloat16 l3 = __float2bfloat16_rn(v.w - __bfloat162float(h3));
    __nv_bfloat162* hp = (__nv_bfloat162*)hi;
    __nv_bfloat162* lp = (__nv_bfloat162*)lo;
    hp[i * 2 + 0] = __nv_bfloat162(h0, h1);
    hp[i * 2 + 1] = __nv_bfloat162(h2, h3);
    lp[i * 2 + 0] = __nv_bfloat162(l0, l1);
    lp[i * 2 + 1] = __nv_bfloat162(l2, l3);
}

// ---------------- mma primitives ----------------
__device__ __forceinline__ void mma16816(float* d, const uint32_t* a, const uint32_t* b) {
    asm volatile(
        "mma.sync.aligned.m16n8k16.row.col.f32.bf16.bf16.f32 "
        "{%0,%1,%2,%3}, {%4,%5,%6,%7}, {%8,%9}, {%0,%1,%2,%3};\n"
        : "+f"(d[0]), "+f"(d[1]), "+f"(d[2]), "+f"(d[3])
        : "r"(a[0]), "r"(a[1]), "r"(a[2]), "r"(a[3]), "r"(b[0]), "r"(b[1]));
}
__device__ __forceinline__ void ldsm4(uint32_t* r, uint32_t addr) {
    asm volatile("ldmatrix.sync.aligned.m8n8.x4.shared.b16 {%0,%1,%2,%3}, [%4];\n"
        : "=r"(r[0]), "=r"(r[1]), "=r"(r[2]), "=r"(r[3]) : "r"(addr));
}
__device__ __forceinline__ void ldsm4t(uint32_t* r, uint32_t addr) {
    asm volatile("ldmatrix.sync.aligned.m8n8.x4.trans.shared.b16 {%0,%1,%2,%3}, [%4];\n"
        : "=r"(r[0]), "=r"(r[1]), "=r"(r[2]), "=r"(r[3]) : "r"(addr));
}
__device__ __forceinline__ void cp16(uint32_t dst, const void* src) {
    asm volatile("cp.async.cg.shared.global [%0], [%1], 16;\n" :: "r"(dst), "l"(src));
}
__device__ __forceinline__ void cp_commit() { asm volatile("cp.async.commit_group;\n"); }
__device__ __forceinline__ void cp_wait1() { asm volatile("cp.async.wait_group 1;\n" ::: "memory"); }

__device__ __forceinline__ void split1(float v, __nv_bfloat16& h, __nv_bfloat16& l) {
    h = __float2bfloat16_rn(v);
    l = __float2bfloat16_rn(v - __bfloat162float(h));
}

// ======================================================================
// Pipelined split-bf16 MMA GEMM NT (cp.async, 3 stages, 1 sync/k-tile)
// C = (Ah+Al)(Wh+Wl)^T, 128x128 block, 8 warps (2m x 4n), k-tile 16.
// blockIdx.z selects target set (QKV fusion).
// ======================================================================
constexpr int ASTR = 24;
constexpr int STG_ARR = 128 * ASTR * 2;   // bytes per array per stage (6144)
constexpr int STG = 4 * STG_ARR;          // bytes per stage (24576)
constexpr int NSTAGE = 3;
constexpr int PIPE_SMEM = NSTAGE * STG;   // 73728

struct GemmTargets {
    const __nv_bfloat16* wh[3];
    const __nv_bfloat16* wl[3];
    const float* bias[3];
    float* c[3];
    __nv_bfloat16* ch[3];
    __nv_bfloat16* cl[3];
};

__global__ __launch_bounds__(256) void gemm_mma_pipe(
    const __nv_bfloat16* __restrict__ Ah, const __nv_bfloat16* __restrict__ Al,
    GemmTargets tg, int M, int N, int K, int act)
{
    extern __shared__ __align__(16) char dsm[];
    const uint32_t sbase = (uint32_t)__cvta_generic_to_shared(dsm);
    const int z = blockIdx.z;
    const __nv_bfloat16* Wh = tg.wh[z];
    const __nv_bfloat16* Wl = tg.wl[z];
    const float* bias = tg.bias[z];
    float* Cp = tg.c[z];
    __nv_bfloat16* Ch = tg.ch[z];
    __nv_bfloat16* Cl = tg.cl[z];
    const float* res = (z == 0 && act == 2) ? nullptr : nullptr; // placeholder
    const float* resp = tg.bias[0] == nullptr ? nullptr : nullptr; (void)resp; (void)res;

    const int bm = blockIdx.y * 128, bn = blockIdx.x * 128;
    const int t = threadIdx.x, lane = t & 31, w = t >> 5;
    const int wm = (w & 1) * 64, wn = (w >> 1) * 32;

    const int grow = t >> 1, gcol = (t & 1) * 8;
    const __nv_bfloat16* pAh = Ah + (size_t)(bm + grow) * K + gcol;
    const __nv_bfloat16* pAl = Al + (size_t)(bm + grow) * K + gcol;
    const __nv_bfloat16* pWh = Wh + (size_t)(bn + grow) * K + gcol;
    const __nv_bfloat16* pWl = Wl + (size_t)(bn + grow) * K + gcol;
    const uint32_t dstoff = (uint32_t)((grow * ASTR + gcol) * 2);

    float acc[4][4][4];
    #pragma unroll
    for (int i = 0; i < 4; i++)
        #pragma unroll
        for (int j = 0; j < 4; j++)
            #pragma unroll
            for (int r = 0; r < 4; r++) acc[i][j][r] = 0.f;

    uint32_t aoff[4], boff[2];
    #pragma unroll
    for (int mi = 0; mi < 4; mi++)
        aoff[mi] = (uint32_t)(((wm + mi * 16 + (lane & 15)) * ASTR + ((lane >> 4) << 3)) * 2);
    #pragma unroll
    for (int ni2 = 0; ni2 < 2; ni2++)
        boff[ni2] = (uint32_t)(((wn + ni2 * 16 + (lane & 7) + ((lane >> 4) << 3)) * ASTR
                               + (((lane >> 3) & 1) << 3)) * 2);

    const int nk = K / 16;

    auto issue = [&](int kt, int slot) {
        if (kt < nk) {
            uint32_t base = sbase + slot * STG + dstoff;
            size_t go = (size_t)kt * 16;
            cp16(base,               pAh + go);
            cp16(base + STG_ARR,     pAl + go);
            cp16(base + 2 * STG_ARR, pWh + go);
            cp16(base + 3 * STG_ARR, pWl + go);
        }
        cp_commit();
    };

    issue(0, 0);
    issue(1, 1);

    for (int kt = 0; kt < nk; kt++) {
        cp_wait1();
        __syncthreads();
        issue(kt + 2, (kt + 2) % NSTAGE);

        const uint32_t sb = sbase + (kt % NSTAGE) * STG;
        uint32_t ah[4][4], al[4][4], bh[4][2], bl[4][2];
        #pragma unroll
        for (int mi = 0; mi < 4; mi++) {
            ldsm4(ah[mi], sb + aoff[mi]);
            ldsm4(al[mi], sb + STG_ARR + aoff[mi]);
        }
        #pragma unroll
        for (int ni2 = 0; ni2 < 2; ni2++) {
            uint32_t t4[4];
            ldsm4(t4, sb + 2 * STG_ARR + boff[ni2]);
            bh[ni2 * 2][0] = t4[0]; bh[ni2 * 2][1] = t4[1];
            bh[ni2 * 2 + 1][0] = t4[2]; bh[ni2 * 2 + 1][1] = t4[3];
            ldsm4(t4, sb + 3 * STG_ARR + boff[ni2]);
            bl[ni2 * 2][0] = t4[0]; bl[ni2 * 2][1] = t4[1];
            bl[ni2 * 2 + 1][0] = t4[2]; bl[ni2 * 2 + 1][1] = t4[3];
        }
        #pragma unroll
        for (int mi = 0; mi < 4; mi++)
            #pragma unroll
            for (int ni = 0; ni < 4; ni++) {
                mma16816(acc[mi][ni], ah[mi], bh[ni]);
                mma16816(acc[mi][ni], ah[mi], bl[ni]);
                mma16816(acc[mi][ni], al[mi], bh[ni]);
            }
    }

    const float* resv = tg.c[z] ? nullptr : nullptr; (void)resv;
    #pragma unroll
    for (int mi = 0; mi < 4; mi++) {
        int m0 = bm + wm + mi * 16 + (lane >> 2);
        #pragma unroll
        for (int ni = 0; ni < 4; ni++) {
            int n = bn + wn + ni * 8 + (lane & 3) * 2;
            float2 v0 = make_float2(acc[mi][ni][0], acc[mi][ni][1]);
            float2 v1 = make_float2(acc[mi][ni][2], acc[mi][ni][3]);
            if (bias) {
                float2 bv = *(const float2*)&bias[n];
                v0.x += bv.x; v0.y += bv.y; v1.x += bv.x; v1.y += bv.y;
            }
            if (act == 1) {
                v0.x = 0.5f * v0.x * (1.f + erff(v0.x * 0.70710678118654752f));
                v0.y = 0.5f * v0.y * (1.f + erff(v0.y * 0.70710678118654752f));
                v1.x = 0.5f * v1.x * (1.f + erff(v1.x * 0.70710678118654752f));
                v1.y = 0.5f * v1.y * (1.f + erff(v1.y * 0.70710678118654752f));
            }
            if (Cp) {
                *(float2*)&Cp[(size_t)m0 * N + n] = v0;
                *(float2*)&Cp[(size_t)(m0 + 8) * N + n] = v1;
            }
            if (Ch) {
                __nv_bfloat16 h0, l0, h1, l1;
                split1(v0.x, h0, l0); split1(v0.y, h1, l1);
                *(__nv_bfloat162*)&Ch[(size_t)m0 * N + n] = __nv_bfloat162(h0, h1);
                *(__nv_bfloat162*)&Cl[(size_t)m0 * N + n] = __nv_bfloat162(l0, l1);
                split1(v1.x, h0, l0); split1(v1.y, h1, l1);
                *(__nv_bfloat162*)&Ch[(size_t)(m0 + 8) * N + n] = __nv_bfloat162(h0, h1);
                *(__nv_bfloat162*)&Cl[(size_t)(m0 + 8) * N + n] = __nv_bfloat162(l0, l1);
            }
        }
    }
}

// Variant with residual (O proj and FFN2): single target, res added.
__global__ __launch_bounds__(256) void gemm_mma_pipe_res(
    const __nv_bfloat16* __restrict__ Ah, const __nv_bfloat16* __restrict__ Al,
    const __nv_bfloat16* __restrict__ Wh, const __nv_bfloat16* __restrict__ Wl,
    const float* __restrict__ bias, const float* __restrict__ res,
    float* __restrict__ Cp, int M, int N, int K)
{
    extern __shared__ __align__(16) char dsm[];
    const uint32_t sbase = (uint32_t)__cvta_generic_to_shared(dsm);
    const int bm = blockIdx.y * 128, bn = blockIdx.x * 128;
    const int t = threadIdx.x, lane = t & 31, w = t >> 5;
    const int wm = (w & 1) * 64, wn = (w >> 1) * 32;

    const int grow = t >> 1, gcol = (t & 1) * 8;
    const __nv_bfloat16* pAh = Ah + (size_t)(bm + grow) * K + gcol;
    const __nv_bfloat16* pAl = Al + (size_t)(bm + grow) * K + gcol;
    const __nv_bfloat16* pWh = Wh + (size_t)(bn + grow) * K + gcol;
    const __nv_bfloat16* pWl = Wl + (size_t)(bn + grow) * K + gcol;
    const uint32_t dstoff = (uint32_t)((grow * ASTR + gcol) * 2);

    float acc[4][4][4];
    #pragma unroll
    for (int i = 0; i < 4; i++)
        #pragma unroll
        for (int j = 0; j < 4; j++)
            #pragma unroll
            for (int r = 0; r < 4; r++) acc[i][j][r] = 0.f;

    uint32_t aoff[4], boff[2];
    #pragma unroll
    for (int mi = 0; mi < 4; mi++)
        aoff[mi] = (uint32_t)(((wm + mi * 16 + (lane & 15)) * ASTR + ((lane >> 4) << 3)) * 2);
    #pragma unroll
    for (int ni2 = 0; ni2 < 2; ni2++)
        boff[ni2] = (uint32_t)(((wn + ni2 * 16 + (lane & 7) + ((lane >> 4) << 3)) * ASTR
                               + (((lane >> 3) & 1) << 3)) * 2);

    const int nk = K / 16;
    auto issue = [&](int kt, int slot) {
        if (kt < nk) {
            uint32_t base = sbase + slot * STG + dstoff;
            size_t go = (size_t)kt * 16;
            cp16(base,               pAh + go);
            cp16(base + STG_ARR,     pAl + go);
            cp16(base + 2 * STG_ARR, pWh + go);
            cp16(base + 3 * STG_ARR, pWl + go);
        }
        cp_commit();
    };
    issue(0, 0);
    issue(1, 1);

    for (int kt = 0; kt < nk; kt++) {
        cp_wait1();
        __syncthreads();
        issue(kt + 2, (kt + 2) % NSTAGE);

        const uint32_t sb = sbase + (kt % NSTAGE) * STG;
        uint32_t ah[4][4], al[4][4], bh[4][2], bl[4][2];
        #pragma unroll
        for (int mi = 0; mi < 4; mi++) {
            ldsm4(ah[mi], sb + aoff[mi]);
            ldsm4(al[mi], sb + STG_ARR + aoff[mi]);
        }
        #pragma unroll
        for (int ni2 = 0; ni2 < 2; ni2++) {
            uint32_t t4[4];
            ldsm4(t4, sb + 2 * STG_ARR + boff[ni2]);
            bh[ni2 * 2][0] = t4[0]; bh[ni2 * 2][1] = t4[1];
            bh[ni2 * 2 + 1][0] = t4[2]; bh[ni2 * 2 + 1][1] = t4[3];
            ldsm4(t4, sb + 3 * STG_ARR + boff[ni2]);
            bl[ni2 * 2][0] = t4[0]; bl[ni2 * 2][1] = t4[1];
            bl[ni2 * 2 + 1][0] = t4[2]; bl[ni2 * 2 + 1][1] = t4[3];
        }
        #pragma unroll
        for (int mi = 0; mi < 4; mi++)
            #pragma unroll
            for (int ni = 0; ni < 4; ni++) {
                mma16816(acc[mi][ni], ah[mi], bh[ni]);
                mma16816(acc[mi][ni], ah[mi], bl[ni]);
                mma16816(acc[mi][ni], al[mi], bh[ni]);
            }
    }

    #pragma unroll
    for (int mi = 0; mi < 4; mi++) {
        int m0 = bm + wm + mi * 16 + (lane >> 2);
        #pragma unroll
        for (int ni = 0; ni < 4; ni++) {
            int n = bn + wn + ni * 8 + (lane & 3) * 2;
            float2 v0 = make_float2(acc[mi][ni][0], acc[mi][ni][1]);
            float2 v1 = make_float2(acc[mi][ni][2], acc[mi][ni][3]);
            float2 bv = *(const float2*)&bias[n];
            v0.x += bv.x; v0.y += bv.y; v1.x += bv.x; v1.y += bv.y;
            float2 r0 = *(const float2*)&res[(size_t)m0 * N + n];
            float2 r1 = *(const float2*)&res[(size_t)(m0 + 8) * N + n];
            v0.x += r0.x; v0.y += r0.y; v1.x += r1.x; v1.y += r1.y;
            *(float2*)&Cp[(size_t)m0 * N + n] = v0;
            *(float2*)&Cp[(size_t)(m0 + 8) * N + n] = v1;
        }
    }
}

// ======================================================================
// Scores MMA: per (b,h) 128x128 q,k tile; K=64 in 2 k-tiles of 32 (static smem)
// ======================================================================
constexpr int QSTR = 40;
__global__ __launch_bounds__(256) void scores_mma(
    const __nv_bfloat16* __restrict__ Qh, const __nv_bfloat16* __restrict__ Ql,
    const __nv_bfloat16* __restrict__ Kh, const __nv_bfloat16* __restrict__ Kl,
    const float* __restrict__ qtab, const int* __restrict__ mask,
    float* __restrict__ scores)
{
    __shared__ __nv_bfloat16 sQh[128 * QSTR], sQl[128 * QSTR];
    __shared__ __nv_bfloat16 sKh[128 * QSTR], sKl[128 * QSTR];
    const int bh = blockIdx.z, b = bh / H, h = bh % H;
    const int q0 = blockIdx.y * 128, k0b = blockIdx.x * 128;
    const int t = threadIdx.x, lane = t & 31, w = t >> 5;
    const int wm = (w & 1) * 64, wn = (w >> 1) * 32;

    const uint32_t bQh = (uint32_t)__cvta_generic_to_shared(sQh);
    const uint32_t bQl = (uint32_t)__cvta_generic_to_shared(sQl);
    const uint32_t bKh = (uint32_t)__cvta_generic_to_shared(sKh);
    const uint32_t bKl = (uint32_t)__cvta_generic_to_shared(sKl);

    float acc[4][4][4];
    #pragma unroll
    for (int i = 0; i < 4; i++)
        #pragma unroll
        for (int j = 0; j < 4; j++)
            #pragma unroll
            for (int r = 0; r < 4; r++) acc[i][j][r] = 0.f;

    uint32_t aoff[4], boff[2];
    #pragma unroll
    for (int mi = 0; mi < 4; mi++)
        aoff[mi] = (uint32_t)(((wm + mi * 16 + (lane & 15)) * QSTR + ((lane >> 4) << 3)) * 2);
    #pragma unroll
    for (int ni2 = 0; ni2 < 2; ni2++)
        boff[ni2] = (uint32_t)(((wn + ni2 * 16 + (lane & 7) + ((lane >> 4) << 3)) * QSTR
                               + (((lane >> 3) & 1) << 3)) * 2);

    for (int kt = 0; kt < 2; kt++) {
        // load 128 rows x 32 cols per array; 2 x 16B per thread per array
        #pragma unroll
        for (int i = 0; i < 2; i++) {
            int idx = t * 2 + i;
            int row = idx >> 2, cseg = (idx & 3) * 8;
            size_t qsrc = ((size_t)(b * S) + q0 + row) * D + h * DH + kt * 32 + cseg;
            size_t ksrc = ((size_t)(b * S) + k0b + row) * D + h * DH + kt * 32 + cseg;
            *(uint4*)&sQh[row * QSTR + cseg] = *(const uint4*)&Qh[qsrc];
            *(uint4*)&sQl[row * QSTR + cseg] = *(const uint4*)&Ql[qsrc];
            *(uint4*)&sKh[row * QSTR + cseg] = *(const uint4*)&Kh[ksrc];
            *(uint4*)&sKl[row * QSTR + cseg] = *(const uint4*)&Kl[ksrc];
        }
        __syncthreads();
        #pragma unroll
        for (int kk2 = 0; kk2 < 2; kk2++) {
            uint32_t koffb = kk2 * 32;
            uint32_t ah[4][4], al[4][4], bhf[4][2], blf[4][2];
            #pragma unroll
            for (int mi = 0; mi < 4; mi++) {
                ldsm4(ah[mi], bQh + aoff[mi] + koffb);
                ldsm4(al[mi], bQl + aoff[mi] + koffb);
            }
            #pragma unroll
            for (int ni2 = 0; ni2 < 2; ni2++) {
                uint32_t t4[4];
                ldsm4(t4, bKh + boff[ni2] + koffb);
                bhf[ni2 * 2][0] = t4[0]; bhf[ni2 * 2][1] = t4[1];
                bhf[ni2 * 2 + 1][0] = t4[2]; bhf[ni2 * 2 + 1][1] = t4[3];
                ldsm4(t4, bKl + boff[ni2] + koffb);
                blf[ni2 * 2][0] = t4[0]; blf[ni2 * 2][1] = t4[1];
                blf[ni2 * 2 + 1][0] = t4[2]; blf[ni2 * 2 + 1][1] = t4[3];
            }
            #pragma unroll
            for (int mi = 0; mi < 4; mi++)
                #pragma unroll
                for (int ni = 0; ni < 4; ni++) {
                    mma16816(acc[mi][ni], ah[mi], bhf[ni]);
                    mma16816(acc[mi][ni], ah[mi], blf[ni]);
                    mma16816(acc[mi][ni], al[mi], bhf[ni]);
                }
        }
        __syncthreads();
    }

    #pragma unroll
    for (int mi = 0; mi < 4; mi++) {
        #pragma unroll
        for (int rr = 0; rr < 2; rr++) {
            int q = q0 + wm + mi * 16 + (lane >> 2) + rr * 8;
            const float* qtr = qtab + (((size_t)b * S + q) * H + h) * NREL;
            size_t rowb = ((size_t)bh * S + q) * S;
            #pragma unroll
            for (int ni = 0; ni < 4; ni++) {
                int k = k0b + wn + ni * 8 + (lane & 3) * 2;
                float vx = acc[mi][ni][rr * 2 + 0];
                float vy = acc[mi][ni][rr * 2 + 1];
                int r0 = k - q; r0 = r0 < -64 ? -64 : (r0 > 64 ? 64 : r0);
                int r1 = k + 1 - q; r1 = r1 < -64 ? -64 : (r1 > 64 ? 64 : r1);
                float mb0 = (1.f - (float)mask[b * S + k]) * -10000.f;
                float mb1 = (1.f - (float)mask[b * S + k + 1]) * -10000.f;
                float2 o;
                o.x = (vx + qtr[r0 + 64]) * SCALE + mb0;
                o.y = (vy + qtr[r1 + 64]) * SCALE + mb1;
                *(float2*)&scores[rowb + k] = o;
            }
        }
    }
}

// ======================================================================
// ctx += probs @ V via MMA. Tile 128q x 64d, k-tile 32. 8 warps (4m x 2n).
// ======================================================================
constexpr int VSTR = 72;
__global__ __launch_bounds__(256) void ctx_pv_mma(
    const __nv_bfloat16* __restrict__ Ph, const __nv_bfloat16* __restrict__ Pl,
    const __nv_bfloat16* __restrict__ Vh, const __nv_bfloat16* __restrict__ Vl,
    float* __restrict__ ctx)
{
    __shared__ __nv_bfloat16 sPh[128 * QSTR], sPl[128 * QSTR];
    __shared__ __nv_bfloat16 sVh[32 * VSTR], sVl[32 * VSTR];
    const int bh = blockIdx.z, b = bh / H, h = bh % H;
    const int q0 = blockIdx.x * 128;
    const int t = threadIdx.x, lane = t & 31, w = t >> 5;
    const int wm = (w & 3) * 32, wn = (w >> 2) * 32;

    const uint32_t bPh = (uint32_t)__cvta_generic_to_shared(sPh);
    const uint32_t bPl = (uint32_t)__cvta_generic_to_shared(sPl);
    const uint32_t bVh = (uint32_t)__cvta_generic_to_shared(sVh);
    const uint32_t bVl = (uint32_t)__cvta_generic_to_shared(sVl);

    float acc[2][4][4];
    #pragma unroll
    for (int i = 0; i < 2; i++)
        #pragma unroll
        for (int j = 0; j < 4; j++)
            #pragma unroll
            for (int r = 0; r < 4; r++) acc[i][j][r] = 0.f;

    uint32_t aoff[2];
    #pragma unroll
    for (int mi = 0; mi < 2; mi++)
        aoff[mi] = (uint32_t)(((wm + mi * 16 + (lane & 15)) * QSTR + ((lane >> 4) << 3)) * 2);

    for (int kt = 0; kt < S / 32; kt++) {
        #pragma unroll
        for (int i = 0; i < 2; i++) {
            int idx = t * 2 + i;
            int row = idx >> 2, cseg = (idx & 3) * 8;
            size_t psrc = ((size_t)bh * S + q0 + row) * S + kt * 32 + cseg;
            *(uint4*)&sPh[row * QSTR + cseg] = *(const uint4*)&Ph[psrc];
            *(uint4*)&sPl[row * QSTR + cseg] = *(const uint4*)&Pl[psrc];
        }
        {
            int row = t >> 3, cseg = (t & 7) * 8;
            size_t vsrc = ((size_t)(b * S) + kt * 32 + row) * D + h * DH + cseg;
            *(uint4*)&sVh[row * VSTR + cseg] = *(const uint4*)&Vh[vsrc];
            *(uint4*)&sVl[row * VSTR + cseg] = *(const uint4*)&Vl[vsrc];
        }
        __syncthreads();
        #pragma unroll
        for (int kk2 = 0; kk2 < 2; kk2++) {
            uint32_t koffb = kk2 * 32;
            uint32_t ah[2][4], al[2][4], bhf[4][2], blf[4][2];
            #pragma unroll
            for (int mi = 0; mi < 2; mi++) {
                ldsm4(ah[mi], bPh + aoff[mi] + koffb);
                ldsm4(al[mi], bPl + aoff[mi] + koffb);
            }
            #pragma unroll
            for (int ni2 = 0; ni2 < 2; ni2++) {
                uint32_t vaddr = (uint32_t)(((kk2 * 16 + (lane & 15)) * VSTR
                                 + wn + ni2 * 16 + (lane >> 4) * 8) * 2);
                uint32_t t4[4];
                ldsm4t(t4, bVh + vaddr);
                bhf[ni2 * 2][0] = t4[0]; bhf[ni2 * 2][1] = t4[1];
                bhf[ni2 * 2 + 1][0] = t4[2]; bhf[ni2 * 2 + 1][1] = t4[3];
                ldsm4t(t4, bVl + vaddr);
                blf[ni2 * 2][0] = t4[0]; blf[ni2 * 2][1] = t4[1];
                blf[ni2 * 2 + 1][0] = t4[2]; blf[ni2 * 2 + 1][1] = t4[3];
            }
            #pragma unroll
            for (int mi = 0; mi < 2; mi++)
                #pragma unroll
                for (int ni = 0; ni < 4; ni++) {
                    mma16816(acc[mi][ni], ah[mi], bhf[ni]);
                    mma16816(acc[mi][ni], ah[mi], blf[ni]);
                    mma16816(acc[mi][ni], al[mi], bhf[ni]);
                }
        }
        __syncthreads();
    }

    #pragma unroll
    for (int mi = 0; mi < 2; mi++) {
        #pragma unroll
        for (int rr = 0; rr < 2; rr++) {
            int q = q0 + wm + mi * 16 + (lane >> 2) + rr * 8;
            size_t rb = ((size_t)(b * S) + q) * D + h * DH;
            #pragma unroll
            for (int ni = 0; ni < 4; ni++) {
                int d = wn + ni * 8 + (lane & 3) * 2;
                float2 cur = *(float2*)&ctx[rb + d];
                cur.x += acc[mi][ni][rr * 2 + 0];
                cur.y += acc[mi][ni][rr * 2 + 1];
                *(float2*)&ctx[rb + d] = cur;
            }
        }
    }
}

// ---------------- embedding + LN (emit fp32 + bf16 hi/lo) ----------------
__global__ __launch_bounds__(256) void embed_ln(
    const int* __restrict__ ids, const int* __restrict__ tti,
    const float* __restrict__ we, const float* __restrict__ te,
    const float* __restrict__ w, const float* __restrict__ bb,
    float* __restrict__ out, __nv_bfloat16* __restrict__ oh,
    __nv_bfloat16* __restrict__ ol)
{
    __shared__ float red[256];
    int m = blockIdx.x, t = threadIdx.x;
    int id = ids[m], t2 = tti[m];
    const float* wr = we + (size_t)id * D;
    const float* tr = te + (size_t)t2 * D;
    float vals[3]; float s = 0.f;
    #pragma unroll
    for (int i = 0; i < 3; i++) { int d = t + i * 256; vals[i] = wr[d] + tr[d]; s += vals[i]; }
    float mean = block_reduce_sum(s, red) * (1.f / D);
    float vs = 0.f;
    #pragma unroll
    for (int i = 0; i < 3; i++) { float dd = vals[i] - mean; vs += dd * dd; }
    float var = block_reduce_sum(vs, red) * (1.f / D);
    float rstd = rsqrtf(var + LN_EPS);
    #pragma unroll
    for (int i = 0; i < 3; i++) {
        int d = t + i * 256;
        float v = (vals[i] - mean) * rstd * w[d] + bb[d];
        out[(size_t)m * D + d] = v;
        __nv_bfloat16 h, l; split1(v, h, l);
        oh[(size_t)m * D + d] = h;
        ol[(size_t)m * D + d] = l;
    }
}

__global__ __launch_bounds__(256) void ln_kernel(
    const float* __restrict__ x, const float* __restrict__ w,
    const float* __restrict__ bb, float* __restrict__ out,
    __nv_bfloat16* __restrict__ oh, __nv_bfloat16* __restrict__ ol)
{
    __shared__ float red[256];
    int m = blockIdx.x, t = threadIdx.x;
    const float* xr = x + (size_t)m * D;
    float vals[3]; float s = 0.f;
    #pragma unroll
    for (int i = 0; i < 3; i++) { vals[i] = xr[t + i * 256]; s += vals[i]; }
    float mean = block_reduce_sum(s, red) * (1.f / D);
    float vs = 0.f;
    #pragma unroll
    for (int i = 0; i < 3; i++) { float dd = vals[i] - mean; vs += dd * dd; }
    float var = block_reduce_sum(vs, red) * (1.f / D);
    float rstd = rsqrtf(var + LN_EPS);
    #pragma unroll
    for (int i = 0; i < 3; i++) {
        int d = t + i * 256;
        float v = (vals[i] - mean) * rstd * w[d] + bb[d];
        out[(size_t)m * D + d] = v;
        __nv_bfloat16 h, l; split1(v, h, l);
        oh[(size_t)m * D + d] = h;
        ol[(size_t)m * D + d] = l;
    }
}

// ---------------- small guarded SIMT GEMMs ----------------
__global__ __launch_bounds__(256) void gemm_nt(
    const float* __restrict__ A, const float* __restrict__ W,
    float* __restrict__ C, int M, int N, int K)
{
    __shared__ float As[16][65];
    __shared__ float Bs[16][65];
    const int bm = blockIdx.y * 64, bn = blockIdx.x * 64;
    const int t = threadIdx.x, tx = t & 15, ty = t >> 4;
    float acc[4][4] = {};
    for (int k0 = 0; k0 < K; k0 += 16) {
        #pragma unroll
        for (int l = 0; l < 4; l++) {
            int idx = t + l * 256;
            int r = idx >> 4, c = idx & 15;
            int m = bm + r, kk = k0 + c;
            As[c][r] = (m < M && kk < K) ? A[(size_t)m * K + kk] : 0.f;
        }
        #pragma unroll
        for (int l = 0; l < 4; l++) {
            int idx = t + l * 256;
            int r = idx >> 4, c = idx & 15;
            int n = bn + r, kk = k0 + c;
            Bs[c][r] = (n < N && kk < K) ? W[(size_t)n * K + kk] : 0.f;
        }
        __syncthreads();
        #pragma unroll
        for (int kk = 0; kk < 16; kk++) {
            float a[4], bv[4];
            #pragma unroll
            for (int i = 0; i < 4; i++) a[i] = As[kk][ty * 4 + i];
            #pragma unroll
            for (int j = 0; j < 4; j++) bv[j] = Bs[kk][tx * 4 + j];
            #pragma unroll
            for (int i = 0; i < 4; i++)
                #pragma unroll
                for (int j = 0; j < 4; j++) acc[i][j] += a[i] * bv[j];
        }
        __syncthreads();
    }
    #pragma unroll
    for (int i = 0; i < 4; i++) {
        int m = bm + ty * 4 + i;
        if (m >= M) continue;
        #pragma unroll
        for (int j = 0; j < 4; j++) {
            int n = bn + tx * 4 + j;
            if (n >= N) continue;
            C[(size_t)m * N + n] = acc[i][j];
        }
    }
}

__global__ __launch_bounds__(256) void gemm_nn_small(
    const float* __restrict__ A, const float* __restrict__ Bm,
    float* __restrict__ C, int M, int N, int K)
{
    __shared__ float As[16][65];
    __shared__ float Bs[16][65];
    const int bm = blockIdx.y * 64, bn = blockIdx.x * 64;
    const int t = threadIdx.x, tx = t & 15, ty = t >> 4;
    float acc[4][4] = {};
    for (int k0 = 0; k0 < K; k0 += 16) {
        #pragma unroll
        for (int l = 0; l < 4; l++) {
            int idx = t + l * 256;
            int r = idx >> 4, c = idx & 15;
            int m = bm + r, kk = k0 + c;
            As[c][r] = (m < M && kk < K) ? A[(size_t)m * K + kk] : 0.f;
        }
        #pragma unroll
        for (int l = 0; l < 4; l++) {
            int idx = t + l * 256;
            int r = idx >> 6, c = idx & 63;
            int kk = k0 + r, n = bn + c;
            Bs[r][c] = (kk < K && n < N) ? Bm[(size_t)kk * N + n] : 0.f;
        }
        __syncthreads();
        #pragma unroll
        for (int kk = 0; kk < 16; kk++) {
            float a[4], bv[4];
            #pragma unroll
            for (int i = 0; i < 4; i++) a[i] = As[kk][ty * 4 + i];
            #pragma unroll
            for (int j = 0; j < 4; j++) bv[j] = Bs[kk][tx * 4 + j];
            #pragma unroll
            for (int i = 0; i < 4; i++)
                #pragma unroll
                for (int j = 0; j < 4; j++) acc[i][j] += a[i] * bv[j];
        }
        __syncthreads();
    }
    #pragma unroll
    for (int i = 0; i < 4; i++) {
        int m = bm + ty * 4 + i;
        if (m >= M) continue;
        #pragma unroll
        for (int j = 0; j < 4; j++) {
            int n = bn + tx * 4 + j;
            if (n >= N) continue;
            C[(size_t)m * N + n] = acc[i][j];
        }
    }
}

// ---------------- softmax: fp32 scores -> bf16 hi/lo probs + ptab ----------------
__global__ __launch_bounds__(256) void softmax_kernel(
    const float* __restrict__ scores,
    __nv_bfloat16* __restrict__ ph, __nv_bfloat16* __restrict__ pl,
    float* __restrict__ ptab)
{
    __shared__ float red[256];
    __shared__ float pr[512];
    const int row = blockIdx.x;
    const int q = row % S, bh = row / S;
    const int b = bh / H, h = bh % H;
    const float* sr = scores + (size_t)row * S;
    const int t = threadIdx.x;
    float v0 = sr[t], v1 = sr[t + 256];

    float m = fmaxf(v0, v1);
    red[t] = m; __syncthreads();
    for (int o = 128; o > 0; o >>= 1) { if (t < o) red[t] = fmaxf(red[t], red[t + o]); __syncthreads(); }
    m = red[0]; __syncthreads();

    float e0 = expf(v0 - m), e1 = expf(v1 - m);
    float s = block_reduce_sum(e0 + e1, red);
    float inv = 1.f / s;
    float p0 = e0 * inv, p1 = e1 * inv;
    pr[t] = p0; pr[t + 256] = p1;

    size_t rb = (size_t)row * S;
    __nv_bfloat16 h0, l0, h1, l1;
    split1(p0, h0, l0); split1(p1, h1, l1);
    ph[rb + t] = h0; ph[rb + t + 256] = h1;
    pl[rb + t] = l0; pl[rb + t + 256] = l1;

    float left = 0.f, right = 0.f;
    if (t <= q - 64)       left += p0;
    if (t + 256 <= q - 64) left += p1;
    if (t >= q + 64)       right += p0;
    if (t + 256 >= q + 64) right += p1;
    left  = block_reduce_sum(left,  red);
    right = block_reduce_sum(right, red);

    size_t pbase = (((size_t)b * S + q) * H + h) * NREL;
    if (t == 0) { ptab[pbase] = left; ptab[pbase + 128] = right; }
    if (t >= 1 && t <= 127) {
        int k = q + t - 64;
        ptab[pbase + t] = (k >= 0 && k < S) ? pr[k] : 0.f;
    }
}

// ---------------- launch ----------------
extern "C" void kernel_launch(void* const* d_in, const int* in_sizes, int n_in,
                              void* d_out, int out_size)
{
    const int*   ids     = (const int*)d_in[0];
    const int*   amask   = (const int*)d_in[1];
    const int*   tti     = (const int*)d_in[2];
    const float* wemb    = (const float*)d_in[3];
    const float* temb    = (const float*)d_in[4];
    const float* elnw    = (const float*)d_in[5];
    const float* elnb    = (const float*)d_in[6];
    const float* qw      = (const float*)d_in[7];
    const float* qb      = (const float*)d_in[8];
    const float* kw      = (const float*)d_in[9];
    const float* kb      = (const float*)d_in[10];
    const float* vw      = (const float*)d_in[11];
    const float* vb      = (const float*)d_in[12];
    const float* rel     = (const float*)d_in[13];
    const float* ow      = (const float*)d_in[14];
    const float* ob      = (const float*)d_in[15];
    const float* alnw    = (const float*)d_in[16];
    const float* alnb    = (const float*)d_in[17];
    const float* iw      = (const float*)d_in[18];
    const float* ib      = (const float*)d_in[19];
    const float* dw      = (const float*)d_in[20];
    const float* db      = (const float*)d_in[21];
    const float* olnw    = (const float*)d_in[22];
    const float* olnb    = (const float*)d_in[23];
    float* out = (float*)d_out;

    float *x, *q, *sc, *qt, *pt, *ctx, *tmp, *attn, *tab;
    cudaGetSymbolAddress((void**)&x,    g_x);
    cudaGetSymbolAddress((void**)&q,    g_q);
    cudaGetSymbolAddress((void**)&sc,   g_scores);
    cudaGetSymbolAddress((void**)&qt,   g_qtab);
    cudaGetSymbolAddress((void**)&pt,   g_ptab);
    cudaGetSymbolAddress((void**)&ctx,  g_ctx);
    cudaGetSymbolAddress((void**)&tmp,  g_tmp);
    cudaGetSymbolAddress((void**)&attn, g_attn);
    cudaGetSymbolAddress((void**)&tab,  g_table);

    __nv_bfloat16 *wqh, *wql, *wkh, *wkl, *wvh, *wvl, *woh, *wol;
    __nv_bfloat16 *wih, *wil, *wdh, *wdl;
    __nv_bfloat16 *xh, *xl, *qh, *ql, *kh, *kl, *vh, *vl, *ah, *al, *ffh, *ffl, *ph, *pl;
    cudaGetSymbolAddress((void**)&wqh, g_wqh); cudaGetSymbolAddress((void**)&wql, g_wql);
    cudaGetSymbolAddress((void**)&wkh, g_wkh); cudaGetSymbolAddress((void**)&wkl, g_wkl);
    cudaGetSymbolAddress((void**)&wvh, g_wvh); cudaGetSymbolAddress((void**)&wvl, g_wvl);
    cudaGetSymbolAddress((void**)&woh, g_woh); cudaGetSymbolAddress((void**)&wol, g_wol);
    cudaGetSymbolAddress((void**)&wih, g_wih); cudaGetSymbolAddress((void**)&wil, g_wil);
    cudaGetSymbolAddress((void**)&wdh, g_wdh); cudaGetSymbolAddress((void**)&wdl, g_wdl);
    cudaGetSymbolAddress((void**)&xh,  g_xh);  cudaGetSymbolAddress((void**)&xl,  g_xl);
    cudaGetSymbolAddress((void**)&qh,  g_qh);  cudaGetSymbolAddress((void**)&ql,  g_ql);
    cudaGetSymbolAddress((void**)&kh,  g_kh);  cudaGetSymbolAddress((void**)&kl,  g_kl);
    cudaGetSymbolAddress((void**)&vh,  g_vh);  cudaGetSymbolAddress((void**)&vl,  g_vl);
    cudaGetSymbolAddress((void**)&ah,  g_ah);  cudaGetSymbolAddress((void**)&al,  g_al);
    cudaGetSymbolAddress((void**)&ffh, g_ffh); cudaGetSymbolAddress((void**)&ffl, g_ffl);
    cudaGetSymbolAddress((void**)&ph,  g_ph);  cudaGetSymbolAddress((void**)&pl,  g_pl);

    // raise dynamic smem limit for pipelined gemms (idempotent; ignore errors)
    cudaFuncSetAttribute(gemm_mma_pipe, cudaFuncAttributeMaxDynamicSharedMemorySize, PIPE_SMEM);
    cudaFuncSetAttribute(gemm_mma_pipe_res, cudaFuncAttributeMaxDynamicSharedMemorySize, PIPE_SMEM);

    build_table<<<(NREL * DH + 255) / 256, 256>>>(rel, tab);
    embed_ln<<<(int)BS, 256>>>(ids, tti, wemb, temb, elnw, elnb, x, xh, xl);

    {
        int n4 = (int)(WSZ / 4), g = (n4 + 255) / 256;
        split_bf16<<<g, 256>>>(qw, wqh, wql, n4);
        split_bf16<<<g, 256>>>(kw, wkh, wkl, n4);
        split_bf16<<<g, 256>>>(vw, wvh, wvl, n4);
        split_bf16<<<g, 256>>>(ow, woh, wol, n4);
        int n4f = (int)(WFF / 4), gf = (n4f + 255) / 256;
        split_bf16<<<gf, 256>>>(iw, wih, wil, n4f);
        split_bf16<<<gf, 256>>>(dw, wdh, wdl, n4f);
    }

    const int nD4 = (int)(BSD / 4), gD = (nD4 + 255) / 256;

    const dim3 gQKV(D / 128, (int)(BS / 128), 3);
    const dim3 gP(D / 128, (int)(BS / 128), 1);
    const dim3 gF1(FF / 128, (int)(BS / 128), 1);
    const dim3 gQT((NREL + 63) / 64, (int)(BS * H / 64));
    const dim3 gCR(1, (int)(BS * H / 64));
    const dim3 gSC(S / 128, S / 128, B * H);
    const dim3 gPV(S / 128, 1, B * H);

    for (int l = 0; l < L; l++) {
        const size_t wo = (size_t)l * D * D;
        const size_t fo = (size_t)l * FF * D;

        // QKV fused (z=3)
        GemmTargets tq = {};
        tq.wh[0] = wqh + wo; tq.wl[0] = wql + wo; tq.bias[0] = qb + l * D;
        tq.c[0] = q; tq.ch[0] = qh; tq.cl[0] = ql;
        tq.wh[1] = wkh + wo; tq.wl[1] = wkl + wo; tq.bias[1] = kb + l * D;
        tq.c[1] = nullptr; tq.ch[1] = kh; tq.cl[1] = kl;
        tq.wh[2] = wvh + wo; tq.wl[2] = wvl + wo; tq.bias[2] = vb + l * D;
        tq.c[2] = nullptr; tq.ch[2] = vh; tq.cl[2] = vl;
        gemm_mma_pipe<<<gQKV, 256, PIPE_SMEM>>>(xh, xl, tq, (int)BS, D, D, 0);

        gemm_nt<<<gQT, 256>>>(q, tab, qt, (int)(BS * H), NREL, DH);

        scores_mma<<<gSC, 256>>>(qh, ql, kh, kl, qt, amask, sc);
        softmax_kernel<<<(int)BHS, 256>>>(sc, ph, pl, pt);

        gemm_nn_small<<<gCR, 256>>>(pt, tab, ctx, (int)(BS * H), DH, NREL);
        ctx_pv_mma<<<gPV, 256>>>(ph, pl, vh, vl, ctx);

        split_bf16<<<gD, 256>>>(ctx, ah, al, nD4);
        gemm_mma_pipe_res<<<gP, 256, PIPE_SMEM>>>(ah, al, woh + wo, wol + wo,
                                                  ob + l * D, x, tmp, (int)BS, D, D);
        ln_kernel<<<(int)BS, 256>>>(tmp, alnw + l * D, alnb + l * D, attn, ah, al);

        // FFN1: gelu, bf16 split output only
        GemmTargets tf = {};
        tf.wh[0] = wih + fo; tf.wl[0] = wil + fo; tf.bias[0] = ib + l * FF;
        tf.c[0] = nullptr; tf.ch[0] = ffh; tf.cl[0] = ffl;
        gemm_mma_pipe<<<gF1, 256, PIPE_SMEM>>>(ah, al, tf, (int)BS, FF, D, 1);

        gemm_mma_pipe_res<<<gP, 256, PIPE_SMEM>>>(ffh, ffl, wdh + fo, wdl + fo,
                                                  db + l * D, attn, tmp, (int)BS, D, FF);
        ln_kernel<<<(int)BS, 256>>>(tmp, olnw + l * D, olnb + l * D,
                                    (l == L - 1) ? out : x, xh, xl);
    }
}